// round 10
// baseline (speedup 1.0000x reference)
#include <cuda_runtime.h>
#include <cuda_bf16.h>
#include <math.h>
#include <stdint.h>

#define NSLICE 16
#define LSEQ   2048
#define DLLM   768
#define EDIM   64
#define EPS    1e-5f
#define NQT    16

// ---------------- device scratch ----------------
__device__ float g_o[NSLICE*LSEQ*EDIM];
__device__ __nv_bfloat16 g_xh[NSLICE*LSEQ*DLLM];
__device__ __nv_bfloat16 g_xl[NSLICE*LSEQ*DLLM];
__device__ __nv_bfloat16 g_qh[NSLICE*LSEQ*EDIM];
__device__ __nv_bfloat16 g_ql[NSLICE*LSEQ*EDIM];
__device__ __nv_bfloat16 g_kh[NSLICE*LSEQ*EDIM];
__device__ __nv_bfloat16 g_kl[NSLICE*LSEQ*EDIM];
__device__ __nv_bfloat16 g_vth[NSLICE*EDIM*LSEQ];   // V^T [s][e][key]
__device__ __nv_bfloat16 g_vtl[NSLICE*EDIM*LSEQ];
__device__ __nv_bfloat16 g_wth[3*EDIM*DLLM];        // W^T [w][n][k]
__device__ __nv_bfloat16 g_wtl[3*EDIM*DLLM];
__device__ float2 g_part[NSLICE*NQT];
__device__ float2 g_stats[NSLICE];

// ---------------- helpers (validated) ----------------
__device__ __forceinline__ uint32_t smem_u32(const void* p) {
    uint32_t a;
    asm("{ .reg .u64 t; cvta.to.shared.u64 t, %1; cvt.u32.u64 %0, t; }" : "=r"(a) : "l"(p));
    return a;
}
__device__ __forceinline__ void ldsm4(uint32_t* r, uint32_t addr) {
    asm volatile("ldmatrix.sync.aligned.m8n8.x4.shared.b16 {%0,%1,%2,%3}, [%4];"
                 : "=r"(r[0]), "=r"(r[1]), "=r"(r[2]), "=r"(r[3]) : "r"(addr) : "memory");
}
__device__ __forceinline__ uint32_t ldsm_addr(uint32_t base, int row0, int kbyte,
                                              int pitch, int lane) {
    return base + (row0 + (lane & 15)) * pitch + kbyte + (lane >> 4) * 16;
}
__device__ __forceinline__ void mma_bf16(float* d, const uint32_t* a,
                                         uint32_t b0, uint32_t b1) {
    asm volatile("mma.sync.aligned.m16n8k16.row.col.f32.bf16.bf16.f32 "
        "{%0,%1,%2,%3}, {%4,%5,%6,%7}, {%8,%9}, {%0,%1,%2,%3};"
        : "+f"(d[0]), "+f"(d[1]), "+f"(d[2]), "+f"(d[3])
        : "r"(a[0]), "r"(a[1]), "r"(a[2]), "r"(a[3]), "r"(b0), "r"(b1));
}
__device__ __forceinline__ void split2(float x0, float x1, uint32_t& h2, uint32_t& l2) {
    __nv_bfloat162 hb = __float22bfloat162_rn(make_float2(x0, x1));
    float2 hf = __bfloat1622float2(hb);
    __nv_bfloat162 lb = __float22bfloat162_rn(make_float2(x0 - hf.x, x1 - hf.y));
    h2 = *reinterpret_cast<uint32_t*>(&hb);
    l2 = *reinterpret_cast<uint32_t*>(&lb);
}
#define CP_ASYNC(dst, src) \
    asm volatile("cp.async.cg.shared.global [%0], [%1], 16;" :: "r"(dst), "l"(src) : "memory")
#define CP_COMMIT() asm volatile("cp.async.commit_group;" ::: "memory")
#define CP_WAIT(n)  asm volatile("cp.async.wait_group %0;" :: "n"(n) : "memory")

// ---------------- kernel 0a: W^T hi/lo split ----------------
__global__ void wsplit_kernel(const float* __restrict__ Wq,
                              const float* __restrict__ Wk,
                              const float* __restrict__ Wv) {
    int idx = blockIdx.x * 256 + threadIdx.x;
    if (idx >= 3 * EDIM * DLLM) return;
    int w = idx / (EDIM * DLLM), rem = idx % (EDIM * DLLM);
    int n = rem / DLLM, k = rem % DLLM;
    const float* W = (w == 0) ? Wq : (w == 1) ? Wk : Wv;
    float x = W[k * EDIM + n];
    __nv_bfloat16 h = __float2bfloat16(x);
    g_wth[idx] = h;
    g_wtl[idx] = __float2bfloat16(x - __bfloat162float(h));
}

// ---------------- kernel 0b: X hi/lo split ----------------
__global__ void xsplit_kernel(const float* __restrict__ X) {
    int base = (blockIdx.x * 256 + threadIdx.x) * 4;
    float4 x = *reinterpret_cast<const float4*>(X + base);
    uint32_t h0, l0, h1, l1;
    split2(x.x, x.y, h0, l0);
    split2(x.z, x.w, h1, l1);
    *reinterpret_cast<uint2*>(g_xh + base) = make_uint2(h0, h1);
    *reinterpret_cast<uint2*>(g_xl + base) = make_uint2(l0, l1);
}

// ----------------------------------------------------------------------------
// Kernel 1: projection, one weight per CTA (w = bid.x % 3), 2 CTAs/SM.
// ----------------------------------------------------------------------------
#define PA0 0              /* AH+AL = 36864 */
#define PA1 36864
#define PB0 73728          /* BH+BL = 18432 */
#define PB1 92160
#define PR_SMEM 110592

__device__ __forceinline__ void proj_prefetch(uint32_t sb, int buf, int s, int row0,
                                              int w, int k0, int tid) {
    const uint32_t ab = sb + (buf ? PA1 : PA0);
    const uint32_t bb = sb + (buf ? PB1 : PB0);
    #pragma unroll
    for (int t = 0; t < 8; ++t) {                      // A: 128r x 64k hi/lo (2048)
        int f = tid + t * 256;
        int sp = f >> 10, ff = f & 1023;
        int rr = ff >> 3, c8 = (ff & 7) * 8;
        const __nv_bfloat16* src = (sp ? g_xl : g_xh)
            + (size_t)s * LSEQ * DLLM + (size_t)(row0 + rr) * DLLM + k0 + c8;
        CP_ASYNC(ab + sp * 18432 + rr * 144 + c8 * 2, src);
    }
    #pragma unroll
    for (int t = 0; t < 4; ++t) {                      // B: 64n x 64k hi/lo (1024)
        int f = tid + t * 256;
        int sp = f >> 9, rem = f & 511;
        int n = rem >> 3, k8 = (rem & 7) * 8;
        const __nv_bfloat16* src = (sp ? g_wtl : g_wth)
            + (size_t)w * EDIM * DLLM + (size_t)n * DLLM + k0 + k8;
        CP_ASYNC(bb + sp * 9216 + n * 144 + k8 * 2, src);
    }
    CP_COMMIT();
}

__global__ __launch_bounds__(256, 2)
void proj_kernel(const float* __restrict__ bq, const float* __restrict__ bk,
                 const float* __restrict__ bv)
{
    extern __shared__ char smem[];
    const uint32_t sb = smem_u32(smem);
    const int tid = threadIdx.x, wid = tid >> 5, lane = tid & 31;
    const int g = lane >> 2, tig = lane & 3;
    const int s = blockIdx.y;
    const int w = blockIdx.x % 3;
    const int row0 = (blockIdx.x / 3) * 128;

    float acc[8][4];
    #pragma unroll
    for (int j = 0; j < 8; ++j)
        #pragma unroll
        for (int q = 0; q < 4; ++q) acc[j][q] = 0.f;

    proj_prefetch(sb, 0, s, row0, w, 0, tid);

    for (int chunk = 0; chunk < 12; ++chunk) {
        const int cur = chunk & 1;
        if (chunk < 11) {
            proj_prefetch(sb, 1 - cur, s, row0, w, (chunk + 1) * 64, tid);
            CP_WAIT(1);
        } else {
            CP_WAIT(0);
        }
        __syncthreads();

        const uint32_t ah = sb + (cur ? PA1 : PA0);
        const uint32_t al = ah + 18432;
        const uint32_t bh = sb + (cur ? PB1 : PB0);
        const uint32_t bl = bh + 9216;
        #pragma unroll
        for (int kb = 0; kb < 4; ++kb) {
            const int kby = kb * 32;
            uint32_t aH[4], aL[4];
            ldsm4(aH, ldsm_addr(ah, wid * 16, kby, 144, lane));
            ldsm4(aL, ldsm_addr(al, wid * 16, kby, 144, lane));
            #pragma unroll
            for (int ntp = 0; ntp < 4; ++ntp) {
                uint32_t bhf[4], blf[4];
                ldsm4(bhf, ldsm_addr(bh, ntp * 16, kby, 144, lane));
                ldsm4(blf, ldsm_addr(bl, ntp * 16, kby, 144, lane));
                mma_bf16(acc[2*ntp],   aH, bhf[0], bhf[2]);
                mma_bf16(acc[2*ntp+1], aH, bhf[1], bhf[3]);
                mma_bf16(acc[2*ntp],   aH, blf[0], blf[2]);
                mma_bf16(acc[2*ntp+1], aH, blf[1], blf[3]);
                mma_bf16(acc[2*ntp],   aL, bhf[0], bhf[2]);
                mma_bf16(acc[2*ntp+1], aL, bhf[1], bhf[3]);
            }
        }
        __syncthreads();
    }

    // epilogue (validated mapping)
    const int r0 = row0 + wid * 16 + g, r1 = r0 + 8;
    const float* bias = (w == 0) ? bq : (w == 1) ? bk : bv;
    #pragma unroll
    for (int j = 0; j < 8; ++j) {
        int c = tig * 2 + 8 * j;
        float b0 = bias[c], b1 = bias[c + 1];
        float v00 = acc[j][0] + b0, v01 = acc[j][1] + b1;
        float v10 = acc[j][2] + b0, v11 = acc[j][3] + b1;
        if (w < 2) {
            __nv_bfloat16* dh = (w ? g_kh : g_qh) + (size_t)s * LSEQ * EDIM;
            __nv_bfloat16* dl = (w ? g_kl : g_ql) + (size_t)s * LSEQ * EDIM;
            uint32_t h0, l0, h1, l1;
            split2(v00, v01, h0, l0);
            split2(v10, v11, h1, l1);
            *reinterpret_cast<uint32_t*>(dh + (size_t)r0 * EDIM + c) = h0;
            *reinterpret_cast<uint32_t*>(dl + (size_t)r0 * EDIM + c) = l0;
            *reinterpret_cast<uint32_t*>(dh + (size_t)r1 * EDIM + c) = h1;
            *reinterpret_cast<uint32_t*>(dl + (size_t)r1 * EDIM + c) = l1;
        } else {
            float vals[4] = {v00, v01, v10, v11};
            #pragma unroll
            for (int q = 0; q < 4; ++q) {
                int e = c + (q & 1);
                int key = (q < 2) ? r0 : r1;
                float v = vals[q];
                __nv_bfloat16 h = __float2bfloat16(v);
                size_t o = ((size_t)s * EDIM + e) * LSEQ + key;
                g_vth[o] = h;
                g_vtl[o] = __float2bfloat16(v - __bfloat162float(h));
            }
        }
    }
}

// ----------------------------------------------------------------------------
// Kernel 2: flash attention, KTILE=64, register P, 2 CTAs/SM.
// ----------------------------------------------------------------------------
#define AT_QH   0
#define AT_QL   18432
#define AT_K0   36864      /* KH+KL = 18432 per buf */
#define AT_K1   55296
#define AT_V0   73728      /* VH+VL = 18432 per buf */
#define AT_V1   92160
#define AT_RED  110592
#define AT_RED2 111616
#define AT_SMEM 112640

__device__ __forceinline__ void attn_prefetch(uint32_t sb, int buf, int s, int kt,
                                              int tid) {
    const uint32_t kb = sb + (buf ? AT_K1 : AT_K0);
    const uint32_t vb = sb + (buf ? AT_V1 : AT_V0);
    #pragma unroll
    for (int t = 0; t < 4; ++t) {                  // K: 64r x 64e hi/lo (1024 chunks)
        int f = tid + t * 256;
        int sp = f >> 9, ff = f & 511;
        int rr = ff >> 3, c8 = (ff & 7) * 8;
        const __nv_bfloat16* src = (sp ? g_kl : g_kh)
            + (size_t)s * LSEQ * EDIM + (size_t)(kt * 64 + rr) * EDIM + c8;
        CP_ASYNC(kb + sp * 9216 + rr * 144 + c8 * 2, src);
    }
    #pragma unroll
    for (int t = 0; t < 4; ++t) {                  // V^T: 64e x 64keys hi/lo (1024)
        int f = tid + t * 256;
        int sp = f >> 9, ff = f & 511;
        int e = ff >> 3, k8 = (ff & 7) * 8;
        const __nv_bfloat16* src = (sp ? g_vtl : g_vth)
            + ((size_t)s * EDIM + e) * LSEQ + kt * 64 + k8;
        CP_ASYNC(vb + sp * 9216 + e * 144 + k8 * 2, src);
    }
    CP_COMMIT();
}

__global__ __launch_bounds__(256, 2)
void attn_kernel()
{
    extern __shared__ char smem[];
    const uint32_t sb = smem_u32(smem);
    const int tid = threadIdx.x, wid = tid >> 5, lane = tid & 31;
    const int g = lane >> 2, tig = lane & 3;
    const int s = blockIdx.y, row0 = blockIdx.x * 128;

    attn_prefetch(sb, 0, s, 0, tid);

    const __nv_bfloat16* Qh = g_qh + (size_t)s * LSEQ * EDIM + (size_t)row0 * EDIM;
    const __nv_bfloat16* Ql = g_ql + (size_t)s * LSEQ * EDIM + (size_t)row0 * EDIM;
    #pragma unroll
    for (int t = 0; t < 8; ++t) {
        int f = tid + t * 256;
        int sp = f >> 10, ff = f & 1023;
        int rr = ff >> 3, c8 = (ff & 7) * 8;
        const __nv_bfloat16* src = (sp ? Ql : Qh) + (size_t)rr * EDIM + c8;
        *reinterpret_cast<uint4*>(smem + (sp ? AT_QL : AT_QH) + rr * 144 + c8 * 2) =
            *reinterpret_cast<const uint4*>(src);
    }

    float O[8][4];
    #pragma unroll
    for (int j = 0; j < 8; ++j)
        #pragma unroll
        for (int q = 0; q < 4; ++q) O[j][q] = 0.f;
    float m0 = -1e30f, m1 = -1e30f, l0 = 0.f, l1 = 0.f;
    const float sc = 0.125f;

    for (int kt = 0; kt < LSEQ / 64; ++kt) {
        const int cur = kt & 1;
        if (kt < LSEQ / 64 - 1) {
            attn_prefetch(sb, 1 - cur, s, kt + 1, tid);
            CP_WAIT(1);
        } else {
            CP_WAIT(0);
        }
        __syncthreads();

        const uint32_t kh = sb + (cur ? AT_K1 : AT_K0);
        const uint32_t kl = kh + 9216;
        const uint32_t vh = sb + (cur ? AT_V1 : AT_V0);
        const uint32_t vl = vh + 9216;

        // ---- S(16x64) = Qh Kh^T + Qh Kl^T + Ql Kh^T ----
        float S[8][4];
        #pragma unroll
        for (int nt = 0; nt < 8; ++nt)
            #pragma unroll
            for (int q = 0; q < 4; ++q) S[nt][q] = 0.f;

        #pragma unroll
        for (int kb = 0; kb < 4; ++kb) {
            const int kby = kb * 32;
            uint32_t aH[4], aL[4];
            ldsm4(aH, ldsm_addr(sb + AT_QH, wid * 16, kby, 144, lane));
            ldsm4(aL, ldsm_addr(sb + AT_QL, wid * 16, kby, 144, lane));
            #pragma unroll
            for (int ntp = 0; ntp < 4; ++ntp) {
                uint32_t bh[4], bl[4];
                ldsm4(bh, ldsm_addr(kh, ntp * 16, kby, 144, lane));
                ldsm4(bl, ldsm_addr(kl, ntp * 16, kby, 144, lane));
                mma_bf16(S[2*ntp],   aH, bh[0], bh[2]);
                mma_bf16(S[2*ntp+1], aH, bh[1], bh[3]);
                mma_bf16(S[2*ntp],   aH, bl[0], bl[2]);
                mma_bf16(S[2*ntp+1], aH, bl[1], bl[3]);
                mma_bf16(S[2*ntp],   aL, bh[0], bh[2]);
                mma_bf16(S[2*ntp+1], aL, bh[1], bh[3]);
            }
        }

        // ---- online softmax ----
        float mx0 = -1e30f, mx1 = -1e30f;
        #pragma unroll
        for (int nt = 0; nt < 8; ++nt) {
            mx0 = fmaxf(mx0, fmaxf(S[nt][0], S[nt][1]));
            mx1 = fmaxf(mx1, fmaxf(S[nt][2], S[nt][3]));
        }
        mx0 = fmaxf(mx0, __shfl_xor_sync(0xffffffffu, mx0, 1));
        mx0 = fmaxf(mx0, __shfl_xor_sync(0xffffffffu, mx0, 2));
        mx1 = fmaxf(mx1, __shfl_xor_sync(0xffffffffu, mx1, 1));
        mx1 = fmaxf(mx1, __shfl_xor_sync(0xffffffffu, mx1, 2));
        float mn0 = fmaxf(m0, sc * mx0), mn1 = fmaxf(m1, sc * mx1);
        float a0 = __expf(m0 - mn0), a1 = __expf(m1 - mn1);
        m0 = mn0; m1 = mn1;
        float s0 = 0.f, s1 = 0.f;
        #pragma unroll
        for (int nt = 0; nt < 8; ++nt) {
            S[nt][0] = __expf(fmaf(sc, S[nt][0], -mn0));
            S[nt][1] = __expf(fmaf(sc, S[nt][1], -mn0));
            S[nt][2] = __expf(fmaf(sc, S[nt][2], -mn1));
            S[nt][3] = __expf(fmaf(sc, S[nt][3], -mn1));
            s0 += S[nt][0] + S[nt][1];
            s1 += S[nt][2] + S[nt][3];
        }
        s0 += __shfl_xor_sync(0xffffffffu, s0, 1);
        s0 += __shfl_xor_sync(0xffffffffu, s0, 2);
        s1 += __shfl_xor_sync(0xffffffffu, s1, 1);
        s1 += __shfl_xor_sync(0xffffffffu, s1, 2);
        l0 = l0 * a0 + s0;
        l1 = l1 * a1 + s1;

        // rescale O
        #pragma unroll
        for (int j = 0; j < 8; ++j) {
            O[j][0] *= a0; O[j][1] *= a0;
            O[j][2] *= a1; O[j][3] *= a1;
        }

        // ---- register P pack + PV (validated mapping) ----
        #pragma unroll
        for (int kb = 0; kb < 4; ++kb) {
            uint32_t ph[4], pl[4];
            split2(S[2*kb][0],   S[2*kb][1],   ph[0], pl[0]);
            split2(S[2*kb][2],   S[2*kb][3],   ph[1], pl[1]);
            split2(S[2*kb+1][0], S[2*kb+1][1], ph[2], pl[2]);
            split2(S[2*kb+1][2], S[2*kb+1][3], ph[3], pl[3]);
            const int kby = kb * 32;
            #pragma unroll
            for (int ntp = 0; ntp < 4; ++ntp) {
                uint32_t vhf[4], vlf[4];
                ldsm4(vhf, ldsm_addr(vh, ntp * 16, kby, 144, lane));
                ldsm4(vlf, ldsm_addr(vl, ntp * 16, kby, 144, lane));
                mma_bf16(O[2*ntp],   ph, vhf[0], vhf[2]);
                mma_bf16(O[2*ntp+1], ph, vhf[1], vhf[3]);
                mma_bf16(O[2*ntp],   ph, vlf[0], vlf[2]);
                mma_bf16(O[2*ntp+1], ph, vlf[1], vlf[3]);
                mma_bf16(O[2*ntp],   pl, vhf[0], vhf[2]);
                mma_bf16(O[2*ntp+1], pl, vhf[1], vhf[3]);
            }
        }
        __syncthreads();
    }

    // ---- finalize ----
    const float inv0 = 1.f / l0, inv1 = 1.f / l1;
    const int r0 = row0 + wid * 16 + g, r1 = r0 + 8;
    float* Og = g_o + (size_t)s * LSEQ * EDIM;
    float lsum = 0.f, lsq = 0.f;
    #pragma unroll
    for (int j = 0; j < 8; ++j) {
        int c = tig * 2 + 8 * j;
        float o00 = O[j][0] * inv0, o01 = O[j][1] * inv0;
        float o10 = O[j][2] * inv1, o11 = O[j][3] * inv1;
        *reinterpret_cast<float2*>(Og + (size_t)r0 * EDIM + c) = make_float2(o00, o01);
        *reinterpret_cast<float2*>(Og + (size_t)r1 * EDIM + c) = make_float2(o10, o11);
        lsum += o00 + o01 + o10 + o11;
        lsq  += o00*o00 + o01*o01 + o10*o10 + o11*o11;
    }

    float* red  = reinterpret_cast<float*>(smem + AT_RED);
    float* red2 = reinterpret_cast<float*>(smem + AT_RED2);
    __syncthreads();
    red[tid] = lsum; red2[tid] = lsq;
    __syncthreads();
    #pragma unroll
    for (int st = 128; st; st >>= 1) {
        if (tid < st) { red[tid] += red[tid + st]; red2[tid] += red2[tid + st]; }
        __syncthreads();
    }
    if (tid == 0) g_part[s * NQT + blockIdx.x] = make_float2(red[0], red2[0]);
}

// ---------------- kernels 3/4 ----------------
__global__ void stats_kernel()
{
    const int s = blockIdx.x, t = threadIdx.x;
    float sum = 0.f, sq = 0.f;
    if (t < NQT) { float2 p = g_part[s * NQT + t]; sum = p.x; sq = p.y; }
    #pragma unroll
    for (int off = 16; off; off >>= 1) {
        sum += __shfl_xor_sync(0xffffffffu, sum, off);
        sq  += __shfl_xor_sync(0xffffffffu, sq,  off);
    }
    if (t == 0) {
        const float n = (float)(LSEQ * EDIM);
        float mu = sum / n;
        float var = sq / n - mu * mu;
        g_stats[s] = make_float2(mu, rsqrtf(var + EPS));
    }
}

__global__ void norm_kernel(float* __restrict__ out)
{
    int base = (blockIdx.x * 256 + threadIdx.x) * 4;
    int s = base / (LSEQ * EDIM);
    float2 st = g_stats[s];
    const float4 o = *reinterpret_cast<const float4*>(&g_o[base]);
    float4 rr;
    rr.x = (o.x - st.x) * st.y; rr.y = (o.y - st.x) * st.y;
    rr.z = (o.z - st.x) * st.y; rr.w = (o.w - st.x) * st.y;
    *reinterpret_cast<float4*>(&out[base]) = rr;
}

// ---------------- host ----------------
extern "C" void kernel_launch(void* const* d_in, const int* in_sizes, int n_in,
                              void* d_out, int out_size)
{
    const float* info = (const float*)d_in[0];
    const float* Wq = (const float*)d_in[1];
    const float* bq = (const float*)d_in[2];
    const float* Wk = (const float*)d_in[3];
    const float* bk = (const float*)d_in[4];
    const float* Wv = (const float*)d_in[5];
    const float* bv = (const float*)d_in[6];
    float* out = (float*)d_out;

    cudaFuncSetAttribute(proj_kernel, cudaFuncAttributeMaxDynamicSharedMemorySize, PR_SMEM);
    cudaFuncSetAttribute(attn_kernel, cudaFuncAttributeMaxDynamicSharedMemorySize, AT_SMEM);

    wsplit_kernel<<<(3 * EDIM * DLLM + 255) / 256, 256>>>(Wq, Wk, Wv);
    xsplit_kernel<<<NSLICE * LSEQ * DLLM / 1024, 256>>>(info);
    proj_kernel<<<dim3(3 * (LSEQ / 128), NSLICE), 256, PR_SMEM>>>(bq, bk, bv);
    attn_kernel<<<dim3(NQT, NSLICE), 256, AT_SMEM>>>();
    stats_kernel<<<NSLICE, 32>>>();
    norm_kernel<<<NSLICE * LSEQ * EDIM / 1024, 256>>>(out);
}

// round 11
// speedup vs baseline: 1.1725x; 1.1725x over previous
#include <cuda_runtime.h>
#include <cuda_bf16.h>
#include <cuda_fp16.h>
#include <math.h>
#include <stdint.h>

#define NSLICE 16
#define LSEQ   2048
#define DLLM   768
#define EDIM   64
#define EPS    1e-5f
#define NQT    16

// ---------------- device scratch ----------------
__device__ float g_o[NSLICE*LSEQ*EDIM];
__device__ __nv_bfloat16 g_xh[NSLICE*LSEQ*DLLM];
__device__ __nv_bfloat16 g_xl[NSLICE*LSEQ*DLLM];
__device__ __half g_qf[NSLICE*LSEQ*EDIM];           // q*0.125, fp16
__device__ __half g_kf[NSLICE*LSEQ*EDIM];           // k, fp16
__device__ __nv_bfloat16 g_vth[NSLICE*EDIM*LSEQ];   // V^T [s][e][key] hi
__device__ __nv_bfloat16 g_vtl[NSLICE*EDIM*LSEQ];   // lo
__device__ __nv_bfloat16 g_wth[3*EDIM*DLLM];        // W^T [w][n][k]
__device__ __nv_bfloat16 g_wtl[3*EDIM*DLLM];
__device__ float2 g_part[NSLICE*NQT];
__device__ float2 g_stats[NSLICE];

// ---------------- helpers (validated) ----------------
__device__ __forceinline__ uint32_t smem_u32(const void* p) {
    uint32_t a;
    asm("{ .reg .u64 t; cvta.to.shared.u64 t, %1; cvt.u32.u64 %0, t; }" : "=r"(a) : "l"(p));
    return a;
}
__device__ __forceinline__ void ldsm4(uint32_t* r, uint32_t addr) {
    asm volatile("ldmatrix.sync.aligned.m8n8.x4.shared.b16 {%0,%1,%2,%3}, [%4];"
                 : "=r"(r[0]), "=r"(r[1]), "=r"(r[2]), "=r"(r[3]) : "r"(addr) : "memory");
}
__device__ __forceinline__ uint32_t ldsm_addr(uint32_t base, int row0, int kbyte,
                                              int pitch, int lane) {
    return base + (row0 + (lane & 15)) * pitch + kbyte + (lane >> 4) * 16;
}
__device__ __forceinline__ void mma_bf16(float* d, const uint32_t* a,
                                         uint32_t b0, uint32_t b1) {
    asm volatile("mma.sync.aligned.m16n8k16.row.col.f32.bf16.bf16.f32 "
        "{%0,%1,%2,%3}, {%4,%5,%6,%7}, {%8,%9}, {%0,%1,%2,%3};"
        : "+f"(d[0]), "+f"(d[1]), "+f"(d[2]), "+f"(d[3])
        : "r"(a[0]), "r"(a[1]), "r"(a[2]), "r"(a[3]), "r"(b0), "r"(b1));
}
__device__ __forceinline__ void mma_f16(float* d, const uint32_t* a,
                                        uint32_t b0, uint32_t b1) {
    asm volatile("mma.sync.aligned.m16n8k16.row.col.f32.f16.f16.f32 "
        "{%0,%1,%2,%3}, {%4,%5,%6,%7}, {%8,%9}, {%0,%1,%2,%3};"
        : "+f"(d[0]), "+f"(d[1]), "+f"(d[2]), "+f"(d[3])
        : "r"(a[0]), "r"(a[1]), "r"(a[2]), "r"(a[3]), "r"(b0), "r"(b1));
}
__device__ __forceinline__ void split2(float x0, float x1, uint32_t& h2, uint32_t& l2) {
    __nv_bfloat162 hb = __float22bfloat162_rn(make_float2(x0, x1));
    float2 hf = __bfloat1622float2(hb);
    __nv_bfloat162 lb = __float22bfloat162_rn(make_float2(x0 - hf.x, x1 - hf.y));
    h2 = *reinterpret_cast<uint32_t*>(&hb);
    l2 = *reinterpret_cast<uint32_t*>(&lb);
}
#define CP_ASYNC(dst, src) \
    asm volatile("cp.async.cg.shared.global [%0], [%1], 16;" :: "r"(dst), "l"(src) : "memory")
#define CP_COMMIT() asm volatile("cp.async.commit_group;" ::: "memory")
#define CP_WAIT(n)  asm volatile("cp.async.wait_group %0;" :: "n"(n) : "memory")

// ---------------- kernel 0a: W^T hi/lo split ----------------
__global__ void wsplit_kernel(const float* __restrict__ Wq,
                              const float* __restrict__ Wk,
                              const float* __restrict__ Wv) {
    int idx = blockIdx.x * 256 + threadIdx.x;
    if (idx >= 3 * EDIM * DLLM) return;
    int w = idx / (EDIM * DLLM), rem = idx % (EDIM * DLLM);
    int n = rem / DLLM, k = rem % DLLM;
    const float* W = (w == 0) ? Wq : (w == 1) ? Wk : Wv;
    float x = W[k * EDIM + n];
    __nv_bfloat16 h = __float2bfloat16(x);
    g_wth[idx] = h;
    g_wtl[idx] = __float2bfloat16(x - __bfloat162float(h));
}

// ---------------- kernel 0b: X hi/lo split ----------------
__global__ void xsplit_kernel(const float* __restrict__ X) {
    int base = (blockIdx.x * 256 + threadIdx.x) * 4;
    float4 x = *reinterpret_cast<const float4*>(X + base);
    uint32_t h0, l0, h1, l1;
    split2(x.x, x.y, h0, l0);
    split2(x.z, x.w, h1, l1);
    *reinterpret_cast<uint2*>(g_xh + base) = make_uint2(h0, h1);
    *reinterpret_cast<uint2*>(g_xl + base) = make_uint2(l0, l1);
}

// ----------------------------------------------------------------------------
// Kernel 1: projection, one weight per CTA (w = bid.x % 3), 2 CTAs/SM.
// ----------------------------------------------------------------------------
#define PA0 0              /* AH+AL = 36864 */
#define PA1 36864
#define PB0 73728          /* BH+BL = 18432 */
#define PB1 92160
#define PR_SMEM 110592

__device__ __forceinline__ void proj_prefetch(uint32_t sb, int buf, int s, int row0,
                                              int w, int k0, int tid) {
    const uint32_t ab = sb + (buf ? PA1 : PA0);
    const uint32_t bb = sb + (buf ? PB1 : PB0);
    #pragma unroll
    for (int t = 0; t < 8; ++t) {                      // A: 128r x 64k hi/lo (2048)
        int f = tid + t * 256;
        int sp = f >> 10, ff = f & 1023;
        int rr = ff >> 3, c8 = (ff & 7) * 8;
        const __nv_bfloat16* src = (sp ? g_xl : g_xh)
            + (size_t)s * LSEQ * DLLM + (size_t)(row0 + rr) * DLLM + k0 + c8;
        CP_ASYNC(ab + sp * 18432 + rr * 144 + c8 * 2, src);
    }
    #pragma unroll
    for (int t = 0; t < 4; ++t) {                      // B: 64n x 64k hi/lo (1024)
        int f = tid + t * 256;
        int sp = f >> 9, rem = f & 511;
        int n = rem >> 3, k8 = (rem & 7) * 8;
        const __nv_bfloat16* src = (sp ? g_wtl : g_wth)
            + (size_t)w * EDIM * DLLM + (size_t)n * DLLM + k0 + k8;
        CP_ASYNC(bb + sp * 9216 + n * 144 + k8 * 2, src);
    }
    CP_COMMIT();
}

__global__ __launch_bounds__(256, 2)
void proj_kernel(const float* __restrict__ bq, const float* __restrict__ bk,
                 const float* __restrict__ bv)
{
    extern __shared__ char smem[];
    const uint32_t sb = smem_u32(smem);
    const int tid = threadIdx.x, wid = tid >> 5, lane = tid & 31;
    const int g = lane >> 2, tig = lane & 3;
    const int s = blockIdx.y;
    const int w = blockIdx.x % 3;
    const int row0 = (blockIdx.x / 3) * 128;

    float acc[8][4];
    #pragma unroll
    for (int j = 0; j < 8; ++j)
        #pragma unroll
        for (int q = 0; q < 4; ++q) acc[j][q] = 0.f;

    proj_prefetch(sb, 0, s, row0, w, 0, tid);

    for (int chunk = 0; chunk < 12; ++chunk) {
        const int cur = chunk & 1;
        if (chunk < 11) {
            proj_prefetch(sb, 1 - cur, s, row0, w, (chunk + 1) * 64, tid);
            CP_WAIT(1);
        } else {
            CP_WAIT(0);
        }
        __syncthreads();

        const uint32_t ah = sb + (cur ? PA1 : PA0);
        const uint32_t al = ah + 18432;
        const uint32_t bh = sb + (cur ? PB1 : PB0);
        const uint32_t bl = bh + 9216;
        #pragma unroll
        for (int kb = 0; kb < 4; ++kb) {
            const int kby = kb * 32;
            uint32_t aH[4], aL[4];
            ldsm4(aH, ldsm_addr(ah, wid * 16, kby, 144, lane));
            ldsm4(aL, ldsm_addr(al, wid * 16, kby, 144, lane));
            #pragma unroll
            for (int ntp = 0; ntp < 4; ++ntp) {
                uint32_t bhf[4], blf[4];
                ldsm4(bhf, ldsm_addr(bh, ntp * 16, kby, 144, lane));
                ldsm4(blf, ldsm_addr(bl, ntp * 16, kby, 144, lane));
                mma_bf16(acc[2*ntp],   aH, bhf[0], bhf[2]);
                mma_bf16(acc[2*ntp+1], aH, bhf[1], bhf[3]);
                mma_bf16(acc[2*ntp],   aH, blf[0], blf[2]);
                mma_bf16(acc[2*ntp+1], aH, blf[1], blf[3]);
                mma_bf16(acc[2*ntp],   aL, bhf[0], bhf[2]);
                mma_bf16(acc[2*ntp+1], aL, bhf[1], bhf[3]);
            }
        }
        __syncthreads();
    }

    // epilogue (validated mapping): rows r0,r1; cols 2*tig+8j
    const int r0 = row0 + wid * 16 + g, r1 = r0 + 8;
    const float* bias = (w == 0) ? bq : (w == 1) ? bk : bv;
    const float mscale = (w == 0) ? 0.125f : 1.f;   // fold softmax scale into q (exact)
    #pragma unroll
    for (int j = 0; j < 8; ++j) {
        int c = tig * 2 + 8 * j;
        float b0 = bias[c], b1 = bias[c + 1];
        float v00 = acc[j][0] + b0, v01 = acc[j][1] + b1;
        float v10 = acc[j][2] + b0, v11 = acc[j][3] + b1;
        if (w < 2) {
            __half* dst = (w ? g_kf : g_qf) + (size_t)s * LSEQ * EDIM;
            __half2 p0 = __floats2half2_rn(v00 * mscale, v01 * mscale);
            __half2 p1 = __floats2half2_rn(v10 * mscale, v11 * mscale);
            *reinterpret_cast<uint32_t*>(dst + (size_t)r0 * EDIM + c) =
                *reinterpret_cast<uint32_t*>(&p0);
            *reinterpret_cast<uint32_t*>(dst + (size_t)r1 * EDIM + c) =
                *reinterpret_cast<uint32_t*>(&p1);
        } else {
            float vals[4] = {v00, v01, v10, v11};
            #pragma unroll
            for (int q = 0; q < 4; ++q) {
                int e = c + (q & 1);
                int key = (q < 2) ? r0 : r1;
                float v = vals[q];
                __nv_bfloat16 h = __float2bfloat16(v);
                size_t o = ((size_t)s * EDIM + e) * LSEQ + key;
                g_vth[o] = h;
                g_vtl[o] = __float2bfloat16(v - __bfloat162float(h));
            }
        }
    }
}

// ----------------------------------------------------------------------------
// Kernel 2: flash attention. QK fp16 single-pass; PV bf16 hi/lo 3-combo.
// KTILE=64, register P, double-buffered cp.async.
// ----------------------------------------------------------------------------
#define AT_QF   0          /* 128 x 144 = 18432 */
#define AT_K0   18432      /* 64 x 144 = 9216 per buf */
#define AT_K1   27648
#define AT_V0   36864      /* VH+VL = 18432 per buf */
#define AT_V1   55296
#define AT_RED  73728
#define AT_RED2 74752
#define AT_SMEM 75776

__device__ __forceinline__ void attn_prefetch(uint32_t sb, int buf, int s, int kt,
                                              int tid) {
    const uint32_t kb = sb + (buf ? AT_K1 : AT_K0);
    const uint32_t vb = sb + (buf ? AT_V1 : AT_V0);
    #pragma unroll
    for (int t = 0; t < 2; ++t) {                  // K: 64r x 64e fp16 (512 chunks)
        int f = tid + t * 256;
        int rr = f >> 3, c8 = (f & 7) * 8;
        const __half* src = g_kf
            + (size_t)s * LSEQ * EDIM + (size_t)(kt * 64 + rr) * EDIM + c8;
        CP_ASYNC(kb + rr * 144 + c8 * 2, src);
    }
    #pragma unroll
    for (int t = 0; t < 4; ++t) {                  // V^T: 64e x 64keys hi/lo (1024)
        int f = tid + t * 256;
        int sp = f >> 9, ff = f & 511;
        int e = ff >> 3, k8 = (ff & 7) * 8;
        const __nv_bfloat16* src = (sp ? g_vtl : g_vth)
            + ((size_t)s * EDIM + e) * LSEQ + kt * 64 + k8;
        CP_ASYNC(vb + sp * 9216 + e * 144 + k8 * 2, src);
    }
    CP_COMMIT();
}

__global__ __launch_bounds__(256, 2)
void attn_kernel()
{
    extern __shared__ char smem[];
    const uint32_t sb = smem_u32(smem);
    const int tid = threadIdx.x, wid = tid >> 5, lane = tid & 31;
    const int g = lane >> 2, tig = lane & 3;
    const int s = blockIdx.y, row0 = blockIdx.x * 128;

    attn_prefetch(sb, 0, s, 0, tid);

    // Q tile (fp16, scale pre-folded): 128r x 64e = 1024 chunks
    const __half* Qf = g_qf + (size_t)s * LSEQ * EDIM + (size_t)row0 * EDIM;
    #pragma unroll
    for (int t = 0; t < 4; ++t) {
        int f = tid + t * 256;
        int rr = f >> 3, c8 = (f & 7) * 8;
        *reinterpret_cast<uint4*>(smem + AT_QF + rr * 144 + c8 * 2) =
            *reinterpret_cast<const uint4*>(Qf + (size_t)rr * EDIM + c8);
    }

    float O[8][4];
    #pragma unroll
    for (int j = 0; j < 8; ++j)
        #pragma unroll
        for (int q = 0; q < 4; ++q) O[j][q] = 0.f;
    float m0 = -1e30f, m1 = -1e30f, l0 = 0.f, l1 = 0.f;

    for (int kt = 0; kt < LSEQ / 64; ++kt) {
        const int cur = kt & 1;
        if (kt < LSEQ / 64 - 1) {
            attn_prefetch(sb, 1 - cur, s, kt + 1, tid);
            CP_WAIT(1);
        } else {
            CP_WAIT(0);
        }
        __syncthreads();

        const uint32_t kf = sb + (cur ? AT_K1 : AT_K0);
        const uint32_t vh = sb + (cur ? AT_V1 : AT_V0);
        const uint32_t vl = vh + 9216;

        // ---- S(16x64) = Q K^T (fp16 single-pass; scale folded into Q) ----
        float S[8][4];
        #pragma unroll
        for (int nt = 0; nt < 8; ++nt)
            #pragma unroll
            for (int q = 0; q < 4; ++q) S[nt][q] = 0.f;

        #pragma unroll
        for (int kb = 0; kb < 4; ++kb) {
            const int kby = kb * 32;
            uint32_t aF[4];
            ldsm4(aF, ldsm_addr(sb + AT_QF, wid * 16, kby, 144, lane));
            #pragma unroll
            for (int ntp = 0; ntp < 4; ++ntp) {
                uint32_t bF[4];
                ldsm4(bF, ldsm_addr(kf, ntp * 16, kby, 144, lane));
                mma_f16(S[2*ntp],   aF, bF[0], bF[2]);
                mma_f16(S[2*ntp+1], aF, bF[1], bF[3]);
            }
        }

        // ---- online softmax (S already scaled) ----
        float mx0 = -1e30f, mx1 = -1e30f;
        #pragma unroll
        for (int nt = 0; nt < 8; ++nt) {
            mx0 = fmaxf(mx0, fmaxf(S[nt][0], S[nt][1]));
            mx1 = fmaxf(mx1, fmaxf(S[nt][2], S[nt][3]));
        }
        mx0 = fmaxf(mx0, __shfl_xor_sync(0xffffffffu, mx0, 1));
        mx0 = fmaxf(mx0, __shfl_xor_sync(0xffffffffu, mx0, 2));
        mx1 = fmaxf(mx1, __shfl_xor_sync(0xffffffffu, mx1, 1));
        mx1 = fmaxf(mx1, __shfl_xor_sync(0xffffffffu, mx1, 2));
        float mn0 = fmaxf(m0, mx0), mn1 = fmaxf(m1, mx1);
        float a0 = __expf(m0 - mn0), a1 = __expf(m1 - mn1);
        m0 = mn0; m1 = mn1;
        float s0 = 0.f, s1 = 0.f;
        #pragma unroll
        for (int nt = 0; nt < 8; ++nt) {
            S[nt][0] = __expf(S[nt][0] - mn0);
            S[nt][1] = __expf(S[nt][1] - mn0);
            S[nt][2] = __expf(S[nt][2] - mn1);
            S[nt][3] = __expf(S[nt][3] - mn1);
            s0 += S[nt][0] + S[nt][1];
            s1 += S[nt][2] + S[nt][3];
        }
        s0 += __shfl_xor_sync(0xffffffffu, s0, 1);
        s0 += __shfl_xor_sync(0xffffffffu, s0, 2);
        s1 += __shfl_xor_sync(0xffffffffu, s1, 1);
        s1 += __shfl_xor_sync(0xffffffffu, s1, 2);
        l0 = l0 * a0 + s0;
        l1 = l1 * a1 + s1;

        // rescale O
        #pragma unroll
        for (int j = 0; j < 8; ++j) {
            O[j][0] *= a0; O[j][1] *= a0;
            O[j][2] *= a1; O[j][3] *= a1;
        }

        // ---- register P pack (bf16 hi/lo) + PV 3-combo (validated) ----
        #pragma unroll
        for (int kb = 0; kb < 4; ++kb) {
            uint32_t ph[4], pl[4];
            split2(S[2*kb][0],   S[2*kb][1],   ph[0], pl[0]);
            split2(S[2*kb][2],   S[2*kb][3],   ph[1], pl[1]);
            split2(S[2*kb+1][0], S[2*kb+1][1], ph[2], pl[2]);
            split2(S[2*kb+1][2], S[2*kb+1][3], ph[3], pl[3]);
            const int kby = kb * 32;
            #pragma unroll
            for (int ntp = 0; ntp < 4; ++ntp) {
                uint32_t vhf[4], vlf[4];
                ldsm4(vhf, ldsm_addr(vh, ntp * 16, kby, 144, lane));
                ldsm4(vlf, ldsm_addr(vl, ntp * 16, kby, 144, lane));
                mma_bf16(O[2*ntp],   ph, vhf[0], vhf[2]);
                mma_bf16(O[2*ntp+1], ph, vhf[1], vhf[3]);
                mma_bf16(O[2*ntp],   ph, vlf[0], vlf[2]);
                mma_bf16(O[2*ntp+1], ph, vlf[1], vlf[3]);
                mma_bf16(O[2*ntp],   pl, vhf[0], vhf[2]);
                mma_bf16(O[2*ntp+1], pl, vhf[1], vhf[3]);
            }
        }
        __syncthreads();
    }

    // ---- finalize ----
    const float inv0 = 1.f / l0, inv1 = 1.f / l1;
    const int r0 = row0 + wid * 16 + g, r1 = r0 + 8;
    float* Og = g_o + (size_t)s * LSEQ * EDIM;
    float lsum = 0.f, lsq = 0.f;
    #pragma unroll
    for (int j = 0; j < 8; ++j) {
        int c = tig * 2 + 8 * j;
        float o00 = O[j][0] * inv0, o01 = O[j][1] * inv0;
        float o10 = O[j][2] * inv1, o11 = O[j][3] * inv1;
        *reinterpret_cast<float2*>(Og + (size_t)r0 * EDIM + c) = make_float2(o00, o01);
        *reinterpret_cast<float2*>(Og + (size_t)r1 * EDIM + c) = make_float2(o10, o11);
        lsum += o00 + o01 + o10 + o11;
        lsq  += o00*o00 + o01*o01 + o10*o10 + o11*o11;
    }

    float* red  = reinterpret_cast<float*>(smem + AT_RED);
    float* red2 = reinterpret_cast<float*>(smem + AT_RED2);
    __syncthreads();
    red[tid] = lsum; red2[tid] = lsq;
    __syncthreads();
    #pragma unroll
    for (int st = 128; st; st >>= 1) {
        if (tid < st) { red[tid] += red[tid + st]; red2[tid] += red2[tid + st]; }
        __syncthreads();
    }
    if (tid == 0) g_part[s * NQT + blockIdx.x] = make_float2(red[0], red2[0]);
}

// ---------------- kernels 3/4 ----------------
__global__ void stats_kernel()
{
    const int s = blockIdx.x, t = threadIdx.x;
    float sum = 0.f, sq = 0.f;
    if (t < NQT) { float2 p = g_part[s * NQT + t]; sum = p.x; sq = p.y; }
    #pragma unroll
    for (int off = 16; off; off >>= 1) {
        sum += __shfl_xor_sync(0xffffffffu, sum, off);
        sq  += __shfl_xor_sync(0xffffffffu, sq,  off);
    }
    if (t == 0) {
        const float n = (float)(LSEQ * EDIM);
        float mu = sum / n;
        float var = sq / n - mu * mu;
        g_stats[s] = make_float2(mu, rsqrtf(var + EPS));
    }
}

__global__ void norm_kernel(float* __restrict__ out)
{
    int base = (blockIdx.x * 256 + threadIdx.x) * 4;
    int s = base / (LSEQ * EDIM);
    float2 st = g_stats[s];
    const float4 o = *reinterpret_cast<const float4*>(&g_o[base]);
    float4 rr;
    rr.x = (o.x - st.x) * st.y; rr.y = (o.y - st.x) * st.y;
    rr.z = (o.z - st.x) * st.y; rr.w = (o.w - st.x) * st.y;
    *reinterpret_cast<float4*>(&out[base]) = rr;
}

// ---------------- host ----------------
extern "C" void kernel_launch(void* const* d_in, const int* in_sizes, int n_in,
                              void* d_out, int out_size)
{
    const float* info = (const float*)d_in[0];
    const float* Wq = (const float*)d_in[1];
    const float* bq = (const float*)d_in[2];
    const float* Wk = (const float*)d_in[3];
    const float* bk = (const float*)d_in[4];
    const float* Wv = (const float*)d_in[5];
    const float* bv = (const float*)d_in[6];
    float* out = (float*)d_out;

    cudaFuncSetAttribute(proj_kernel, cudaFuncAttributeMaxDynamicSharedMemorySize, PR_SMEM);
    cudaFuncSetAttribute(attn_kernel, cudaFuncAttributeMaxDynamicSharedMemorySize, AT_SMEM);

    wsplit_kernel<<<(3 * EDIM * DLLM + 255) / 256, 256>>>(Wq, Wk, Wv);
    xsplit_kernel<<<NSLICE * LSEQ * DLLM / 1024, 256>>>(info);
    proj_kernel<<<dim3(3 * (LSEQ / 128), NSLICE), 256, PR_SMEM>>>(bq, bk, bv);
    attn_kernel<<<dim3(NQT, NSLICE), 256, AT_SMEM>>>();
    stats_kernel<<<NSLICE, 32>>>();
    norm_kernel<<<NSLICE * LSEQ * EDIM / 1024, 256>>>(out);
}

// round 12
// speedup vs baseline: 1.3050x; 1.1130x over previous
#include <cuda_runtime.h>
#include <cuda_bf16.h>
#include <cuda_fp16.h>
#include <math.h>
#include <stdint.h>

#define NSLICE 16
#define LSEQ   2048
#define DLLM   768
#define EDIM   64
#define EPS    1e-5f
#define NQT    16

// ---------------- device scratch ----------------
__device__ float g_o[NSLICE*LSEQ*EDIM];
__device__ __nv_bfloat16 g_xh[NSLICE*LSEQ*DLLM];
__device__ __nv_bfloat16 g_xl[NSLICE*LSEQ*DLLM];
__device__ __half g_qf[NSLICE*LSEQ*EDIM];           // q*0.125, fp16
__device__ __half g_kf[NSLICE*LSEQ*EDIM];           // k, fp16
__device__ __half g_vth[NSLICE*EDIM*LSEQ];          // V^T [s][e][key] fp16 hi
__device__ __half g_vtl[NSLICE*EDIM*LSEQ];          // fp16 lo (residual)
__device__ __nv_bfloat16 g_wth[3*EDIM*DLLM];        // W^T [w][n][k]
__device__ __nv_bfloat16 g_wtl[3*EDIM*DLLM];
__device__ float2 g_part[NSLICE*NQT];
__device__ float2 g_stats[NSLICE];

// ---------------- helpers (validated) ----------------
__device__ __forceinline__ uint32_t smem_u32(const void* p) {
    uint32_t a;
    asm("{ .reg .u64 t; cvta.to.shared.u64 t, %1; cvt.u32.u64 %0, t; }" : "=r"(a) : "l"(p));
    return a;
}
__device__ __forceinline__ void ldsm4(uint32_t* r, uint32_t addr) {
    asm volatile("ldmatrix.sync.aligned.m8n8.x4.shared.b16 {%0,%1,%2,%3}, [%4];"
                 : "=r"(r[0]), "=r"(r[1]), "=r"(r[2]), "=r"(r[3]) : "r"(addr) : "memory");
}
__device__ __forceinline__ uint32_t ldsm_addr(uint32_t base, int row0, int kbyte,
                                              int pitch, int lane) {
    return base + (row0 + (lane & 15)) * pitch + kbyte + (lane >> 4) * 16;
}
__device__ __forceinline__ void mma_bf16(float* d, const uint32_t* a,
                                         uint32_t b0, uint32_t b1) {
    asm volatile("mma.sync.aligned.m16n8k16.row.col.f32.bf16.bf16.f32 "
        "{%0,%1,%2,%3}, {%4,%5,%6,%7}, {%8,%9}, {%0,%1,%2,%3};"
        : "+f"(d[0]), "+f"(d[1]), "+f"(d[2]), "+f"(d[3])
        : "r"(a[0]), "r"(a[1]), "r"(a[2]), "r"(a[3]), "r"(b0), "r"(b1));
}
__device__ __forceinline__ void mma_f16(float* d, const uint32_t* a,
                                        uint32_t b0, uint32_t b1) {
    asm volatile("mma.sync.aligned.m16n8k16.row.col.f32.f16.f16.f32 "
        "{%0,%1,%2,%3}, {%4,%5,%6,%7}, {%8,%9}, {%0,%1,%2,%3};"
        : "+f"(d[0]), "+f"(d[1]), "+f"(d[2]), "+f"(d[3])
        : "r"(a[0]), "r"(a[1]), "r"(a[2]), "r"(a[3]), "r"(b0), "r"(b1));
}
__device__ __forceinline__ void split2(float x0, float x1, uint32_t& h2, uint32_t& l2) {
    __nv_bfloat162 hb = __float22bfloat162_rn(make_float2(x0, x1));
    float2 hf = __bfloat1622float2(hb);
    __nv_bfloat162 lb = __float22bfloat162_rn(make_float2(x0 - hf.x, x1 - hf.y));
    h2 = *reinterpret_cast<uint32_t*>(&hb);
    l2 = *reinterpret_cast<uint32_t*>(&lb);
}
__device__ __forceinline__ uint32_t pack_h2(float x0, float x1) {
    __half2 h = __floats2half2_rn(x0, x1);
    return *reinterpret_cast<uint32_t*>(&h);
}
#define CP_ASYNC(dst, src) \
    asm volatile("cp.async.cg.shared.global [%0], [%1], 16;" :: "r"(dst), "l"(src) : "memory")
#define CP_COMMIT() asm volatile("cp.async.commit_group;" ::: "memory")
#define CP_WAIT(n)  asm volatile("cp.async.wait_group %0;" :: "n"(n) : "memory")

// ---------------- kernel 0a: W^T hi/lo split ----------------
__global__ void wsplit_kernel(const float* __restrict__ Wq,
                              const float* __restrict__ Wk,
                              const float* __restrict__ Wv) {
    int idx = blockIdx.x * 256 + threadIdx.x;
    if (idx >= 3 * EDIM * DLLM) return;
    int w = idx / (EDIM * DLLM), rem = idx % (EDIM * DLLM);
    int n = rem / DLLM, k = rem % DLLM;
    const float* W = (w == 0) ? Wq : (w == 1) ? Wk : Wv;
    float x = W[k * EDIM + n];
    __nv_bfloat16 h = __float2bfloat16(x);
    g_wth[idx] = h;
    g_wtl[idx] = __float2bfloat16(x - __bfloat162float(h));
}

// ---------------- kernel 0b: X hi/lo split ----------------
__global__ void xsplit_kernel(const float* __restrict__ X) {
    int base = (blockIdx.x * 256 + threadIdx.x) * 4;
    float4 x = *reinterpret_cast<const float4*>(X + base);
    uint32_t h0, l0, h1, l1;
    split2(x.x, x.y, h0, l0);
    split2(x.z, x.w, h1, l1);
    *reinterpret_cast<uint2*>(g_xh + base) = make_uint2(h0, h1);
    *reinterpret_cast<uint2*>(g_xl + base) = make_uint2(l0, l1);
}

// ----------------------------------------------------------------------------
// Kernel 1: projection, one weight per CTA (w = bid.x % 3), 2 CTAs/SM.
// ----------------------------------------------------------------------------
#define PA0 0              /* AH+AL = 36864 */
#define PA1 36864
#define PB0 73728          /* BH+BL = 18432 */
#define PB1 92160
#define PR_SMEM 110592

__device__ __forceinline__ void proj_prefetch(uint32_t sb, int buf, int s, int row0,
                                              int w, int k0, int tid) {
    const uint32_t ab = sb + (buf ? PA1 : PA0);
    const uint32_t bb = sb + (buf ? PB1 : PB0);
    #pragma unroll
    for (int t = 0; t < 8; ++t) {                      // A: 128r x 64k hi/lo (2048)
        int f = tid + t * 256;
        int sp = f >> 10, ff = f & 1023;
        int rr = ff >> 3, c8 = (ff & 7) * 8;
        const __nv_bfloat16* src = (sp ? g_xl : g_xh)
            + (size_t)s * LSEQ * DLLM + (size_t)(row0 + rr) * DLLM + k0 + c8;
        CP_ASYNC(ab + sp * 18432 + rr * 144 + c8 * 2, src);
    }
    #pragma unroll
    for (int t = 0; t < 4; ++t) {                      // B: 64n x 64k hi/lo (1024)
        int f = tid + t * 256;
        int sp = f >> 9, rem = f & 511;
        int n = rem >> 3, k8 = (rem & 7) * 8;
        const __nv_bfloat16* src = (sp ? g_wtl : g_wth)
            + (size_t)w * EDIM * DLLM + (size_t)n * DLLM + k0 + k8;
        CP_ASYNC(bb + sp * 9216 + n * 144 + k8 * 2, src);
    }
    CP_COMMIT();
}

__global__ __launch_bounds__(256, 2)
void proj_kernel(const float* __restrict__ bq, const float* __restrict__ bk,
                 const float* __restrict__ bv)
{
    extern __shared__ char smem[];
    const uint32_t sb = smem_u32(smem);
    const int tid = threadIdx.x, wid = tid >> 5, lane = tid & 31;
    const int g = lane >> 2, tig = lane & 3;
    const int s = blockIdx.y;
    const int w = blockIdx.x % 3;
    const int row0 = (blockIdx.x / 3) * 128;

    float acc[8][4];
    #pragma unroll
    for (int j = 0; j < 8; ++j)
        #pragma unroll
        for (int q = 0; q < 4; ++q) acc[j][q] = 0.f;

    proj_prefetch(sb, 0, s, row0, w, 0, tid);

    for (int chunk = 0; chunk < 12; ++chunk) {
        const int cur = chunk & 1;
        if (chunk < 11) {
            proj_prefetch(sb, 1 - cur, s, row0, w, (chunk + 1) * 64, tid);
            CP_WAIT(1);
        } else {
            CP_WAIT(0);
        }
        __syncthreads();

        const uint32_t ah = sb + (cur ? PA1 : PA0);
        const uint32_t al = ah + 18432;
        const uint32_t bh = sb + (cur ? PB1 : PB0);
        const uint32_t bl = bh + 9216;
        #pragma unroll
        for (int kb = 0; kb < 4; ++kb) {
            const int kby = kb * 32;
            uint32_t aH[4], aL[4];
            ldsm4(aH, ldsm_addr(ah, wid * 16, kby, 144, lane));
            ldsm4(aL, ldsm_addr(al, wid * 16, kby, 144, lane));
            #pragma unroll
            for (int ntp = 0; ntp < 4; ++ntp) {
                uint32_t bhf[4], blf[4];
                ldsm4(bhf, ldsm_addr(bh, ntp * 16, kby, 144, lane));
                ldsm4(blf, ldsm_addr(bl, ntp * 16, kby, 144, lane));
                mma_bf16(acc[2*ntp],   aH, bhf[0], bhf[2]);
                mma_bf16(acc[2*ntp+1], aH, bhf[1], bhf[3]);
                mma_bf16(acc[2*ntp],   aH, blf[0], blf[2]);
                mma_bf16(acc[2*ntp+1], aH, blf[1], blf[3]);
                mma_bf16(acc[2*ntp],   aL, bhf[0], bhf[2]);
                mma_bf16(acc[2*ntp+1], aL, bhf[1], bhf[3]);
            }
        }
        __syncthreads();
    }

    // epilogue (validated mapping): rows r0,r1; cols 2*tig+8j
    const int r0 = row0 + wid * 16 + g, r1 = r0 + 8;
    const float* bias = (w == 0) ? bq : (w == 1) ? bk : bv;
    const float mscale = (w == 0) ? 0.125f : 1.f;   // fold softmax scale into q
    #pragma unroll
    for (int j = 0; j < 8; ++j) {
        int c = tig * 2 + 8 * j;
        float b0 = bias[c], b1 = bias[c + 1];
        float v00 = acc[j][0] + b0, v01 = acc[j][1] + b1;
        float v10 = acc[j][2] + b0, v11 = acc[j][3] + b1;
        if (w < 2) {
            __half* dst = (w ? g_kf : g_qf) + (size_t)s * LSEQ * EDIM;
            *reinterpret_cast<uint32_t*>(dst + (size_t)r0 * EDIM + c) =
                pack_h2(v00 * mscale, v01 * mscale);
            *reinterpret_cast<uint32_t*>(dst + (size_t)r1 * EDIM + c) =
                pack_h2(v10 * mscale, v11 * mscale);
        } else {
            float vals[4] = {v00, v01, v10, v11};
            #pragma unroll
            for (int q = 0; q < 4; ++q) {
                int e = c + (q & 1);
                int key = (q < 2) ? r0 : r1;
                float v = vals[q];
                __half h = __float2half_rn(v);
                size_t o = ((size_t)s * EDIM + e) * LSEQ + key;
                g_vth[o] = h;
                g_vtl[o] = __float2half_rn(v - __half2float(h));
            }
        }
    }
}

// ----------------------------------------------------------------------------
// Kernel 2: flash attention. QK fp16 single-pass; PV fp16 P + fp16 V hi/lo 2-combo.
// ----------------------------------------------------------------------------
#define AT_QF   0          /* 128 x 144 = 18432 */
#define AT_K0   18432      /* 64 x 144 = 9216 per buf */
#define AT_K1   27648
#define AT_V0   36864      /* VH+VL = 18432 per buf */
#define AT_V1   55296
#define AT_RED  73728
#define AT_RED2 74752
#define AT_SMEM 75776

__device__ __forceinline__ void attn_prefetch(uint32_t sb, int buf, int s, int kt,
                                              int tid) {
    const uint32_t kb = sb + (buf ? AT_K1 : AT_K0);
    const uint32_t vb = sb + (buf ? AT_V1 : AT_V0);
    #pragma unroll
    for (int t = 0; t < 2; ++t) {                  // K: 64r x 64e fp16 (512 chunks)
        int f = tid + t * 256;
        int rr = f >> 3, c8 = (f & 7) * 8;
        const __half* src = g_kf
            + (size_t)s * LSEQ * EDIM + (size_t)(kt * 64 + rr) * EDIM + c8;
        CP_ASYNC(kb + rr * 144 + c8 * 2, src);
    }
    #pragma unroll
    for (int t = 0; t < 4; ++t) {                  // V^T: 64e x 64keys fp16 hi/lo (1024)
        int f = tid + t * 256;
        int sp = f >> 9, ff = f & 511;
        int e = ff >> 3, k8 = (ff & 7) * 8;
        const __half* src = (sp ? g_vtl : g_vth)
            + ((size_t)s * EDIM + e) * LSEQ + kt * 64 + k8;
        CP_ASYNC(vb + sp * 9216 + e * 144 + k8 * 2, src);
    }
    CP_COMMIT();
}

__global__ __launch_bounds__(256, 2)
void attn_kernel()
{
    extern __shared__ char smem[];
    const uint32_t sb = smem_u32(smem);
    const int tid = threadIdx.x, wid = tid >> 5, lane = tid & 31;
    const int g = lane >> 2, tig = lane & 3;
    const int s = blockIdx.y, row0 = blockIdx.x * 128;

    attn_prefetch(sb, 0, s, 0, tid);

    // Q tile (fp16, scale pre-folded): 128r x 64e = 1024 chunks
    const __half* Qf = g_qf + (size_t)s * LSEQ * EDIM + (size_t)row0 * EDIM;
    #pragma unroll
    for (int t = 0; t < 4; ++t) {
        int f = tid + t * 256;
        int rr = f >> 3, c8 = (f & 7) * 8;
        *reinterpret_cast<uint4*>(smem + AT_QF + rr * 144 + c8 * 2) =
            *reinterpret_cast<const uint4*>(Qf + (size_t)rr * EDIM + c8);
    }

    float O[8][4];
    #pragma unroll
    for (int j = 0; j < 8; ++j)
        #pragma unroll
        for (int q = 0; q < 4; ++q) O[j][q] = 0.f;
    float m0 = -1e30f, m1 = -1e30f, l0 = 0.f, l1 = 0.f;

    for (int kt = 0; kt < LSEQ / 64; ++kt) {
        const int cur = kt & 1;
        if (kt < LSEQ / 64 - 1) {
            attn_prefetch(sb, 1 - cur, s, kt + 1, tid);
            CP_WAIT(1);
        } else {
            CP_WAIT(0);
        }
        __syncthreads();

        const uint32_t kf = sb + (cur ? AT_K1 : AT_K0);
        const uint32_t vh = sb + (cur ? AT_V1 : AT_V0);
        const uint32_t vl = vh + 9216;

        // ---- S(16x64) = Q K^T (fp16 single-pass; scale folded into Q) ----
        float S[8][4];
        #pragma unroll
        for (int nt = 0; nt < 8; ++nt)
            #pragma unroll
            for (int q = 0; q < 4; ++q) S[nt][q] = 0.f;

        #pragma unroll
        for (int kb = 0; kb < 4; ++kb) {
            const int kby = kb * 32;
            uint32_t aF[4];
            ldsm4(aF, ldsm_addr(sb + AT_QF, wid * 16, kby, 144, lane));
            #pragma unroll
            for (int ntp = 0; ntp < 4; ++ntp) {
                uint32_t bF[4];
                ldsm4(bF, ldsm_addr(kf, ntp * 16, kby, 144, lane));
                mma_f16(S[2*ntp],   aF, bF[0], bF[2]);
                mma_f16(S[2*ntp+1], aF, bF[1], bF[3]);
            }
        }

        // ---- online softmax (S already scaled) ----
        float mx0 = -1e30f, mx1 = -1e30f;
        #pragma unroll
        for (int nt = 0; nt < 8; ++nt) {
            mx0 = fmaxf(mx0, fmaxf(S[nt][0], S[nt][1]));
            mx1 = fmaxf(mx1, fmaxf(S[nt][2], S[nt][3]));
        }
        mx0 = fmaxf(mx0, __shfl_xor_sync(0xffffffffu, mx0, 1));
        mx0 = fmaxf(mx0, __shfl_xor_sync(0xffffffffu, mx0, 2));
        mx1 = fmaxf(mx1, __shfl_xor_sync(0xffffffffu, mx1, 1));
        mx1 = fmaxf(mx1, __shfl_xor_sync(0xffffffffu, mx1, 2));
        float mn0 = fmaxf(m0, mx0), mn1 = fmaxf(m1, mx1);
        float a0 = __expf(m0 - mn0), a1 = __expf(m1 - mn1);
        m0 = mn0; m1 = mn1;
        float s0 = 0.f, s1 = 0.f;
        #pragma unroll
        for (int nt = 0; nt < 8; ++nt) {
            S[nt][0] = __expf(S[nt][0] - mn0);
            S[nt][1] = __expf(S[nt][1] - mn0);
            S[nt][2] = __expf(S[nt][2] - mn1);
            S[nt][3] = __expf(S[nt][3] - mn1);
            s0 += S[nt][0] + S[nt][1];
            s1 += S[nt][2] + S[nt][3];
        }
        s0 += __shfl_xor_sync(0xffffffffu, s0, 1);
        s0 += __shfl_xor_sync(0xffffffffu, s0, 2);
        s1 += __shfl_xor_sync(0xffffffffu, s1, 1);
        s1 += __shfl_xor_sync(0xffffffffu, s1, 2);
        l0 = l0 * a0 + s0;
        l1 = l1 * a1 + s1;

        // rescale O
        #pragma unroll
        for (int j = 0; j < 8; ++j) {
            O[j][0] *= a0; O[j][1] *= a0;
            O[j][2] *= a1; O[j][3] *= a1;
        }

        // ---- register P pack (fp16) + PV 2-combo: O += P Vh + P Vl ----
        // A-frag mapping identical to validated bf16-hi pack, dtype fp16.
        #pragma unroll
        for (int kb = 0; kb < 4; ++kb) {
            uint32_t pf[4];
            pf[0] = pack_h2(S[2*kb][0],   S[2*kb][1]);
            pf[1] = pack_h2(S[2*kb][2],   S[2*kb][3]);
            pf[2] = pack_h2(S[2*kb+1][0], S[2*kb+1][1]);
            pf[3] = pack_h2(S[2*kb+1][2], S[2*kb+1][3]);
            const int kby = kb * 32;
            #pragma unroll
            for (int ntp = 0; ntp < 4; ++ntp) {
                uint32_t vhf[4], vlf[4];
                ldsm4(vhf, ldsm_addr(vh, ntp * 16, kby, 144, lane));
                ldsm4(vlf, ldsm_addr(vl, ntp * 16, kby, 144, lane));
                mma_f16(O[2*ntp],   pf, vhf[0], vhf[2]);
                mma_f16(O[2*ntp+1], pf, vhf[1], vhf[3]);
                mma_f16(O[2*ntp],   pf, vlf[0], vlf[2]);
                mma_f16(O[2*ntp+1], pf, vlf[1], vlf[3]);
            }
        }
        __syncthreads();
    }

    // ---- finalize ----
    const float inv0 = 1.f / l0, inv1 = 1.f / l1;
    const int r0 = row0 + wid * 16 + g, r1 = r0 + 8;
    float* Og = g_o + (size_t)s * LSEQ * EDIM;
    float lsum = 0.f, lsq = 0.f;
    #pragma unroll
    for (int j = 0; j < 8; ++j) {
        int c = tig * 2 + 8 * j;
        float o00 = O[j][0] * inv0, o01 = O[j][1] * inv0;
        float o10 = O[j][2] * inv1, o11 = O[j][3] * inv1;
        *reinterpret_cast<float2*>(Og + (size_t)r0 * EDIM + c) = make_float2(o00, o01);
        *reinterpret_cast<float2*>(Og + (size_t)r1 * EDIM + c) = make_float2(o10, o11);
        lsum += o00 + o01 + o10 + o11;
        lsq  += o00*o00 + o01*o01 + o10*o10 + o11*o11;
    }

    float* red  = reinterpret_cast<float*>(smem + AT_RED);
    float* red2 = reinterpret_cast<float*>(smem + AT_RED2);
    __syncthreads();
    red[tid] = lsum; red2[tid] = lsq;
    __syncthreads();
    #pragma unroll
    for (int st = 128; st; st >>= 1) {
        if (tid < st) { red[tid] += red[tid + st]; red2[tid] += red2[tid + st]; }
        __syncthreads();
    }
    if (tid == 0) g_part[s * NQT + blockIdx.x] = make_float2(red[0], red2[0]);
}

// ---------------- kernels 3/4 ----------------
__global__ void stats_kernel()
{
    const int s = blockIdx.x, t = threadIdx.x;
    float sum = 0.f, sq = 0.f;
    if (t < NQT) { float2 p = g_part[s * NQT + t]; sum = p.x; sq = p.y; }
    #pragma unroll
    for (int off = 16; off; off >>= 1) {
        sum += __shfl_xor_sync(0xffffffffu, sum, off);
        sq  += __shfl_xor_sync(0xffffffffu, sq,  off);
    }
    if (t == 0) {
        const float n = (float)(LSEQ * EDIM);
        float mu = sum / n;
        float var = sq / n - mu * mu;
        g_stats[s] = make_float2(mu, rsqrtf(var + EPS));
    }
}

__global__ void norm_kernel(float* __restrict__ out)
{
    int base = (blockIdx.x * 256 + threadIdx.x) * 4;
    int s = base / (LSEQ * EDIM);
    float2 st = g_stats[s];
    const float4 o = *reinterpret_cast<const float4*>(&g_o[base]);
    float4 rr;
    rr.x = (o.x - st.x) * st.y; rr.y = (o.y - st.x) * st.y;
    rr.z = (o.z - st.x) * st.y; rr.w = (o.w - st.x) * st.y;
    *reinterpret_cast<float4*>(&out[base]) = rr;
}

// ---------------- host ----------------
extern "C" void kernel_launch(void* const* d_in, const int* in_sizes, int n_in,
                              void* d_out, int out_size)
{
    const float* info = (const float*)d_in[0];
    const float* Wq = (const float*)d_in[1];
    const float* bq = (const float*)d_in[2];
    const float* Wk = (const float*)d_in[3];
    const float* bk = (const float*)d_in[4];
    const float* Wv = (const float*)d_in[5];
    const float* bv = (const float*)d_in[6];
    float* out = (float*)d_out;

    cudaFuncSetAttribute(proj_kernel, cudaFuncAttributeMaxDynamicSharedMemorySize, PR_SMEM);
    cudaFuncSetAttribute(attn_kernel, cudaFuncAttributeMaxDynamicSharedMemorySize, AT_SMEM);

    wsplit_kernel<<<(3 * EDIM * DLLM + 255) / 256, 256>>>(Wq, Wk, Wv);
    xsplit_kernel<<<NSLICE * LSEQ * DLLM / 1024, 256>>>(info);
    proj_kernel<<<dim3(3 * (LSEQ / 128), NSLICE), 256, PR_SMEM>>>(bq, bk, bv);
    attn_kernel<<<dim3(NQT, NSLICE), 256, AT_SMEM>>>();
    stats_kernel<<<NSLICE, 32>>>();
    norm_kernel<<<NSLICE * LSEQ * EDIM / 1024, 256>>>(out);
}

// round 13
// speedup vs baseline: 2.0236x; 1.5507x over previous
#include <cuda_runtime.h>
#include <cuda_fp16.h>
#include <math.h>
#include <stdint.h>

#define NSLICE 16
#define LSEQ   2048
#define DLLM   768
#define EDIM   64
#define EPS    1e-5f
#define NQT    16

// ---------------- device scratch ----------------
__device__ float g_o[NSLICE*LSEQ*EDIM];
__device__ __half g_xf[NSLICE*LSEQ*DLLM];    // info fp16
__device__ __half g_qf[NSLICE*LSEQ*EDIM];    // q*0.125 fp16
__device__ __half g_kf[NSLICE*LSEQ*EDIM];    // k fp16
__device__ __half g_vt[NSLICE*EDIM*LSEQ];    // V^T [s][e][key] fp16
__device__ __half g_wf[3*EDIM*DLLM];         // W^T [w][n][k] fp16
__device__ float2 g_part[NSLICE*NQT];
__device__ float2 g_stats[NSLICE];

// ---------------- helpers (validated) ----------------
__device__ __forceinline__ uint32_t smem_u32(const void* p) {
    uint32_t a;
    asm("{ .reg .u64 t; cvta.to.shared.u64 t, %1; cvt.u32.u64 %0, t; }" : "=r"(a) : "l"(p));
    return a;
}
__device__ __forceinline__ void ldsm4(uint32_t* r, uint32_t addr) {
    asm volatile("ldmatrix.sync.aligned.m8n8.x4.shared.b16 {%0,%1,%2,%3}, [%4];"
                 : "=r"(r[0]), "=r"(r[1]), "=r"(r[2]), "=r"(r[3]) : "r"(addr) : "memory");
}
__device__ __forceinline__ uint32_t ldsm_addr(uint32_t base, int row0, int kbyte,
                                              int pitch, int lane) {
    return base + (row0 + (lane & 15)) * pitch + kbyte + (lane >> 4) * 16;
}
__device__ __forceinline__ void mma_f16(float* d, const uint32_t* a,
                                        uint32_t b0, uint32_t b1) {
    asm volatile("mma.sync.aligned.m16n8k16.row.col.f32.f16.f16.f32 "
        "{%0,%1,%2,%3}, {%4,%5,%6,%7}, {%8,%9}, {%0,%1,%2,%3};"
        : "+f"(d[0]), "+f"(d[1]), "+f"(d[2]), "+f"(d[3])
        : "r"(a[0]), "r"(a[1]), "r"(a[2]), "r"(a[3]), "r"(b0), "r"(b1));
}
__device__ __forceinline__ uint32_t pack_h2(float x0, float x1) {
    __half2 h = __floats2half2_rn(x0, x1);
    return *reinterpret_cast<uint32_t*>(&h);
}
#define CP_ASYNC(dst, src) \
    asm volatile("cp.async.cg.shared.global [%0], [%1], 16;" :: "r"(dst), "l"(src) : "memory")
#define CP_COMMIT() asm volatile("cp.async.commit_group;" ::: "memory")
#define CP_WAIT(n)  asm volatile("cp.async.wait_group %0;" :: "n"(n) : "memory")

// ---------------- kernel 0a: W^T fp16 ----------------
__global__ void wsplit_kernel(const float* __restrict__ Wq,
                              const float* __restrict__ Wk,
                              const float* __restrict__ Wv) {
    int idx = blockIdx.x * 256 + threadIdx.x;
    if (idx >= 3 * EDIM * DLLM) return;
    int w = idx / (EDIM * DLLM), rem = idx % (EDIM * DLLM);
    int n = rem / DLLM, k = rem % DLLM;
    const float* W = (w == 0) ? Wq : (w == 1) ? Wk : Wv;
    g_wf[idx] = __float2half_rn(W[k * EDIM + n]);
}

// ---------------- kernel 0b: X fp16 ----------------
__global__ void xsplit_kernel(const float* __restrict__ X) {
    int base = (blockIdx.x * 256 + threadIdx.x) * 4;
    float4 x = *reinterpret_cast<const float4*>(X + base);
    uint2 out;
    out.x = pack_h2(x.x, x.y);
    out.y = pack_h2(x.z, x.w);
    *reinterpret_cast<uint2*>(g_xf + base) = out;
}

// ----------------------------------------------------------------------------
// Kernel 1: projection fp16 single-pass; one weight per CTA; double-buffered.
// CTA = 128 rows x 64 cols; K chunked by 64; 8 warps x 16 rows.
// ----------------------------------------------------------------------------
#define PA0 0              /* 128 x 144 = 18432 */
#define PA1 18432
#define PB0 36864          /* 64 x 144 = 9216 */
#define PB1 46080
#define PR_SMEM 55296

__device__ __forceinline__ void proj_prefetch(uint32_t sb, int buf, int s, int row0,
                                              int w, int k0, int tid) {
    const uint32_t ab = sb + (buf ? PA1 : PA0);
    const uint32_t bb = sb + (buf ? PB1 : PB0);
    #pragma unroll
    for (int t = 0; t < 4; ++t) {                      // A: 128r x 64k fp16 (1024)
        int f = tid + t * 256;
        int rr = f >> 3, c8 = (f & 7) * 8;
        const __half* src = g_xf
            + (size_t)s * LSEQ * DLLM + (size_t)(row0 + rr) * DLLM + k0 + c8;
        CP_ASYNC(ab + rr * 144 + c8 * 2, src);
    }
    #pragma unroll
    for (int t = 0; t < 2; ++t) {                      // B: 64n x 64k fp16 (512)
        int f = tid + t * 256;
        int n = f >> 3, k8 = (f & 7) * 8;
        const __half* src = g_wf
            + (size_t)w * EDIM * DLLM + (size_t)n * DLLM + k0 + k8;
        CP_ASYNC(bb + n * 144 + k8 * 2, src);
    }
    CP_COMMIT();
}

__global__ __launch_bounds__(256, 2)
void proj_kernel(const float* __restrict__ bq, const float* __restrict__ bk,
                 const float* __restrict__ bv)
{
    extern __shared__ char smem[];
    const uint32_t sb = smem_u32(smem);
    const int tid = threadIdx.x, wid = tid >> 5, lane = tid & 31;
    const int g = lane >> 2, tig = lane & 3;
    const int s = blockIdx.y;
    const int w = blockIdx.x % 3;
    const int row0 = (blockIdx.x / 3) * 128;

    float acc[8][4];
    #pragma unroll
    for (int j = 0; j < 8; ++j)
        #pragma unroll
        for (int q = 0; q < 4; ++q) acc[j][q] = 0.f;

    proj_prefetch(sb, 0, s, row0, w, 0, tid);

    for (int chunk = 0; chunk < 12; ++chunk) {
        const int cur = chunk & 1;
        if (chunk < 11) {
            proj_prefetch(sb, 1 - cur, s, row0, w, (chunk + 1) * 64, tid);
            CP_WAIT(1);
        } else {
            CP_WAIT(0);
        }
        __syncthreads();

        const uint32_t ab = sb + (cur ? PA1 : PA0);
        const uint32_t bb = sb + (cur ? PB1 : PB0);
        #pragma unroll
        for (int kb = 0; kb < 4; ++kb) {
            const int kby = kb * 32;
            uint32_t aF[4];
            ldsm4(aF, ldsm_addr(ab, wid * 16, kby, 144, lane));
            #pragma unroll
            for (int ntp = 0; ntp < 4; ++ntp) {
                uint32_t bF[4];
                ldsm4(bF, ldsm_addr(bb, ntp * 16, kby, 144, lane));
                mma_f16(acc[2*ntp],   aF, bF[0], bF[2]);
                mma_f16(acc[2*ntp+1], aF, bF[1], bF[3]);
            }
        }
        __syncthreads();
    }

    // epilogue (validated mapping): rows r0,r1; cols 2*tig+8j
    const int r0 = row0 + wid * 16 + g, r1 = r0 + 8;
    const float* bias = (w == 0) ? bq : (w == 1) ? bk : bv;
    const float mscale = (w == 0) ? 0.125f : 1.f;   // fold softmax scale into q
    #pragma unroll
    for (int j = 0; j < 8; ++j) {
        int c = tig * 2 + 8 * j;
        float b0 = bias[c], b1 = bias[c + 1];
        float v00 = acc[j][0] + b0, v01 = acc[j][1] + b1;
        float v10 = acc[j][2] + b0, v11 = acc[j][3] + b1;
        if (w < 2) {
            __half* dst = (w ? g_kf : g_qf) + (size_t)s * LSEQ * EDIM;
            *reinterpret_cast<uint32_t*>(dst + (size_t)r0 * EDIM + c) =
                pack_h2(v00 * mscale, v01 * mscale);
            *reinterpret_cast<uint32_t*>(dst + (size_t)r1 * EDIM + c) =
                pack_h2(v10 * mscale, v11 * mscale);
        } else {
            float vals[4] = {v00, v01, v10, v11};
            #pragma unroll
            for (int q = 0; q < 4; ++q) {
                int e = c + (q & 1);
                int key = (q < 2) ? r0 : r1;
                g_vt[((size_t)s * EDIM + e) * LSEQ + key] = __float2half_rn(vals[q]);
            }
        }
    }
}

// ----------------------------------------------------------------------------
// Kernel 2: flash attention, full fp16 single-pass (QK and PV).
// ----------------------------------------------------------------------------
#define AT_QF   0          /* 128 x 144 = 18432 */
#define AT_K0   18432      /* 64 x 144 = 9216 per buf */
#define AT_K1   27648
#define AT_V0   36864      /* 64 x 144 = 9216 per buf */
#define AT_V1   46080
#define AT_RED  55296
#define AT_RED2 56320
#define AT_SMEM 57344

__device__ __forceinline__ void attn_prefetch(uint32_t sb, int buf, int s, int kt,
                                              int tid) {
    const uint32_t kb = sb + (buf ? AT_K1 : AT_K0);
    const uint32_t vb = sb + (buf ? AT_V1 : AT_V0);
    #pragma unroll
    for (int t = 0; t < 2; ++t) {                  // K: 64r x 64e fp16 (512)
        int f = tid + t * 256;
        int rr = f >> 3, c8 = (f & 7) * 8;
        const __half* src = g_kf
            + (size_t)s * LSEQ * EDIM + (size_t)(kt * 64 + rr) * EDIM + c8;
        CP_ASYNC(kb + rr * 144 + c8 * 2, src);
    }
    #pragma unroll
    for (int t = 0; t < 2; ++t) {                  // V^T: 64e x 64keys fp16 (512)
        int f = tid + t * 256;
        int e = f >> 3, k8 = (f & 7) * 8;
        const __half* src = g_vt
            + ((size_t)s * EDIM + e) * LSEQ + kt * 64 + k8;
        CP_ASYNC(vb + e * 144 + k8 * 2, src);
    }
    CP_COMMIT();
}

__global__ __launch_bounds__(256, 2)
void attn_kernel()
{
    extern __shared__ char smem[];
    const uint32_t sb = smem_u32(smem);
    const int tid = threadIdx.x, wid = tid >> 5, lane = tid & 31;
    const int g = lane >> 2, tig = lane & 3;
    const int s = blockIdx.y, row0 = blockIdx.x * 128;

    attn_prefetch(sb, 0, s, 0, tid);

    // Q tile (fp16, scale pre-folded): 1024 chunks
    const __half* Qf = g_qf + (size_t)s * LSEQ * EDIM + (size_t)row0 * EDIM;
    #pragma unroll
    for (int t = 0; t < 4; ++t) {
        int f = tid + t * 256;
        int rr = f >> 3, c8 = (f & 7) * 8;
        *reinterpret_cast<uint4*>(smem + AT_QF + rr * 144 + c8 * 2) =
            *reinterpret_cast<const uint4*>(Qf + (size_t)rr * EDIM + c8);
    }

    float O[8][4];
    #pragma unroll
    for (int j = 0; j < 8; ++j)
        #pragma unroll
        for (int q = 0; q < 4; ++q) O[j][q] = 0.f;
    float m0 = -1e30f, m1 = -1e30f, l0 = 0.f, l1 = 0.f;

    for (int kt = 0; kt < LSEQ / 64; ++kt) {
        const int cur = kt & 1;
        if (kt < LSEQ / 64 - 1) {
            attn_prefetch(sb, 1 - cur, s, kt + 1, tid);
            CP_WAIT(1);
        } else {
            CP_WAIT(0);
        }
        __syncthreads();

        const uint32_t kf = sb + (cur ? AT_K1 : AT_K0);
        const uint32_t vf = sb + (cur ? AT_V1 : AT_V0);

        // ---- S(16x64) = Q K^T ----
        float S[8][4];
        #pragma unroll
        for (int nt = 0; nt < 8; ++nt)
            #pragma unroll
            for (int q = 0; q < 4; ++q) S[nt][q] = 0.f;

        #pragma unroll
        for (int kb = 0; kb < 4; ++kb) {
            const int kby = kb * 32;
            uint32_t aF[4];
            ldsm4(aF, ldsm_addr(sb + AT_QF, wid * 16, kby, 144, lane));
            #pragma unroll
            for (int ntp = 0; ntp < 4; ++ntp) {
                uint32_t bF[4];
                ldsm4(bF, ldsm_addr(kf, ntp * 16, kby, 144, lane));
                mma_f16(S[2*ntp],   aF, bF[0], bF[2]);
                mma_f16(S[2*ntp+1], aF, bF[1], bF[3]);
            }
        }

        // ---- online softmax ----
        float mx0 = -1e30f, mx1 = -1e30f;
        #pragma unroll
        for (int nt = 0; nt < 8; ++nt) {
            mx0 = fmaxf(mx0, fmaxf(S[nt][0], S[nt][1]));
            mx1 = fmaxf(mx1, fmaxf(S[nt][2], S[nt][3]));
        }
        mx0 = fmaxf(mx0, __shfl_xor_sync(0xffffffffu, mx0, 1));
        mx0 = fmaxf(mx0, __shfl_xor_sync(0xffffffffu, mx0, 2));
        mx1 = fmaxf(mx1, __shfl_xor_sync(0xffffffffu, mx1, 1));
        mx1 = fmaxf(mx1, __shfl_xor_sync(0xffffffffu, mx1, 2));
        float mn0 = fmaxf(m0, mx0), mn1 = fmaxf(m1, mx1);
        float a0 = __expf(m0 - mn0), a1 = __expf(m1 - mn1);
        m0 = mn0; m1 = mn1;
        float s0 = 0.f, s1 = 0.f;
        #pragma unroll
        for (int nt = 0; nt < 8; ++nt) {
            S[nt][0] = __expf(S[nt][0] - mn0);
            S[nt][1] = __expf(S[nt][1] - mn0);
            S[nt][2] = __expf(S[nt][2] - mn1);
            S[nt][3] = __expf(S[nt][3] - mn1);
            s0 += S[nt][0] + S[nt][1];
            s1 += S[nt][2] + S[nt][3];
        }
        s0 += __shfl_xor_sync(0xffffffffu, s0, 1);
        s0 += __shfl_xor_sync(0xffffffffu, s0, 2);
        s1 += __shfl_xor_sync(0xffffffffu, s1, 1);
        s1 += __shfl_xor_sync(0xffffffffu, s1, 2);
        l0 = l0 * a0 + s0;
        l1 = l1 * a1 + s1;

        // rescale O
        #pragma unroll
        for (int j = 0; j < 8; ++j) {
            O[j][0] *= a0; O[j][1] *= a0;
            O[j][2] *= a1; O[j][3] *= a1;
        }

        // ---- register P pack (fp16) + PV single-pass ----
        #pragma unroll
        for (int kb = 0; kb < 4; ++kb) {
            uint32_t pf[4];
            pf[0] = pack_h2(S[2*kb][0],   S[2*kb][1]);
            pf[1] = pack_h2(S[2*kb][2],   S[2*kb][3]);
            pf[2] = pack_h2(S[2*kb+1][0], S[2*kb+1][1]);
            pf[3] = pack_h2(S[2*kb+1][2], S[2*kb+1][3]);
            const int kby = kb * 32;
            #pragma unroll
            for (int ntp = 0; ntp < 4; ++ntp) {
                uint32_t vF[4];
                ldsm4(vF, ldsm_addr(vf, ntp * 16, kby, 144, lane));
                mma_f16(O[2*ntp],   pf, vF[0], vF[2]);
                mma_f16(O[2*ntp+1], pf, vF[1], vF[3]);
            }
        }
        __syncthreads();
    }

    // ---- finalize ----
    const float inv0 = 1.f / l0, inv1 = 1.f / l1;
    const int r0 = row0 + wid * 16 + g, r1 = r0 + 8;
    float* Og = g_o + (size_t)s * LSEQ * EDIM;
    float lsum = 0.f, lsq = 0.f;
    #pragma unroll
    for (int j = 0; j < 8; ++j) {
        int c = tig * 2 + 8 * j;
        float o00 = O[j][0] * inv0, o01 = O[j][1] * inv0;
        float o10 = O[j][2] * inv1, o11 = O[j][3] * inv1;
        *reinterpret_cast<float2*>(Og + (size_t)r0 * EDIM + c) = make_float2(o00, o01);
        *reinterpret_cast<float2*>(Og + (size_t)r1 * EDIM + c) = make_float2(o10, o11);
        lsum += o00 + o01 + o10 + o11;
        lsq  += o00*o00 + o01*o01 + o10*o10 + o11*o11;
    }

    float* red  = reinterpret_cast<float*>(smem + AT_RED);
    float* red2 = reinterpret_cast<float*>(smem + AT_RED2);
    __syncthreads();
    red[tid] = lsum; red2[tid] = lsq;
    __syncthreads();
    #pragma unroll
    for (int st = 128; st; st >>= 1) {
        if (tid < st) { red[tid] += red[tid + st]; red2[tid] += red2[tid + st]; }
        __syncthreads();
    }
    if (tid == 0) g_part[s * NQT + blockIdx.x] = make_float2(red[0], red2[0]);
}

// ---------------- kernels 3/4 ----------------
__global__ void stats_kernel()
{
    const int s = blockIdx.x, t = threadIdx.x;
    float sum = 0.f, sq = 0.f;
    if (t < NQT) { float2 p = g_part[s * NQT + t]; sum = p.x; sq = p.y; }
    #pragma unroll
    for (int off = 16; off; off >>= 1) {
        sum += __shfl_xor_sync(0xffffffffu, sum, off);
        sq  += __shfl_xor_sync(0xffffffffu, sq,  off);
    }
    if (t == 0) {
        const float n = (float)(LSEQ * EDIM);
        float mu = sum / n;
        float var = sq / n - mu * mu;
        g_stats[s] = make_float2(mu, rsqrtf(var + EPS));
    }
}

__global__ void norm_kernel(float* __restrict__ out)
{
    int base = (blockIdx.x * 256 + threadIdx.x) * 4;
    int s = base / (LSEQ * EDIM);
    float2 st = g_stats[s];
    const float4 o = *reinterpret_cast<const float4*>(&g_o[base]);
    float4 rr;
    rr.x = (o.x - st.x) * st.y; rr.y = (o.y - st.x) * st.y;
    rr.z = (o.z - st.x) * st.y; rr.w = (o.w - st.x) * st.y;
    *reinterpret_cast<float4*>(&out[base]) = rr;
}

// ---------------- host ----------------
extern "C" void kernel_launch(void* const* d_in, const int* in_sizes, int n_in,
                              void* d_out, int out_size)
{
    const float* info = (const float*)d_in[0];
    const float* Wq = (const float*)d_in[1];
    const float* bq = (const float*)d_in[2];
    const float* Wk = (const float*)d_in[3];
    const float* bk = (const float*)d_in[4];
    const float* Wv = (const float*)d_in[5];
    const float* bv = (const float*)d_in[6];
    float* out = (float*)d_out;

    cudaFuncSetAttribute(proj_kernel, cudaFuncAttributeMaxDynamicSharedMemorySize, PR_SMEM);
    cudaFuncSetAttribute(attn_kernel, cudaFuncAttributeMaxDynamicSharedMemorySize, AT_SMEM);

    wsplit_kernel<<<(3 * EDIM * DLLM + 255) / 256, 256>>>(Wq, Wk, Wv);
    xsplit_kernel<<<NSLICE * LSEQ * DLLM / 1024, 256>>>(info);
    proj_kernel<<<dim3(3 * (LSEQ / 128), NSLICE), 256, PR_SMEM>>>(bq, bk, bv);
    attn_kernel<<<dim3(NQT, NSLICE), 256, AT_SMEM>>>();
    stats_kernel<<<NSLICE, 32>>>();
    norm_kernel<<<NSLICE * LSEQ * EDIM / 1024, 256>>>(out);
}

// round 14
// speedup vs baseline: 2.2391x; 1.1065x over previous
#include <cuda_runtime.h>
#include <cuda_fp16.h>
#include <math.h>
#include <stdint.h>

#define NSLICE 16
#define LSEQ   2048
#define DLLM   768
#define EDIM   64
#define EPS    1e-5f
#define NQT    16
#define QLOG2SCALE (0.125f * 1.4426950408889634f)   // fold softmax scale + log2(e)

// ---------------- device scratch ----------------
__device__ float g_o[NSLICE*LSEQ*EDIM];
__device__ __half g_qf[NSLICE*LSEQ*EDIM];    // q*0.125*log2e, fp16
__device__ __half g_kf[NSLICE*LSEQ*EDIM];    // k fp16
__device__ __half g_vt[NSLICE*EDIM*LSEQ];    // V^T [s][e][key] fp16
__device__ __half g_wf[3*EDIM*DLLM];         // W^T [w][n][k] fp16
__device__ float2 g_part[NSLICE*NQT];
__device__ float2 g_stats[NSLICE];

// ---------------- helpers (validated) ----------------
__device__ __forceinline__ uint32_t smem_u32(const void* p) {
    uint32_t a;
    asm("{ .reg .u64 t; cvta.to.shared.u64 t, %1; cvt.u32.u64 %0, t; }" : "=r"(a) : "l"(p));
    return a;
}
__device__ __forceinline__ void ldsm4(uint32_t* r, uint32_t addr) {
    asm volatile("ldmatrix.sync.aligned.m8n8.x4.shared.b16 {%0,%1,%2,%3}, [%4];"
                 : "=r"(r[0]), "=r"(r[1]), "=r"(r[2]), "=r"(r[3]) : "r"(addr) : "memory");
}
__device__ __forceinline__ uint32_t ldsm_addr(uint32_t base, int row0, int kbyte,
                                              int pitch, int lane) {
    return base + (row0 + (lane & 15)) * pitch + kbyte + (lane >> 4) * 16;
}
__device__ __forceinline__ void mma_f16(float* d, const uint32_t* a,
                                        uint32_t b0, uint32_t b1) {
    asm volatile("mma.sync.aligned.m16n8k16.row.col.f32.f16.f16.f32 "
        "{%0,%1,%2,%3}, {%4,%5,%6,%7}, {%8,%9}, {%0,%1,%2,%3};"
        : "+f"(d[0]), "+f"(d[1]), "+f"(d[2]), "+f"(d[3])
        : "r"(a[0]), "r"(a[1]), "r"(a[2]), "r"(a[3]), "r"(b0), "r"(b1));
}
__device__ __forceinline__ uint32_t pack_h2(float x0, float x1) {
    __half2 h = __floats2half2_rn(x0, x1);
    return *reinterpret_cast<uint32_t*>(&h);
}
#define CP_ASYNC(dst, src) \
    asm volatile("cp.async.cg.shared.global [%0], [%1], 16;" :: "r"(dst), "l"(src) : "memory")
#define CP_COMMIT() asm volatile("cp.async.commit_group;" ::: "memory")
#define CP_WAIT(n)  asm volatile("cp.async.wait_group %0;" :: "n"(n) : "memory")

// ---------------- kernel 0: W^T fp16 ----------------
__global__ void wsplit_kernel(const float* __restrict__ Wq,
                              const float* __restrict__ Wk,
                              const float* __restrict__ Wv) {
    int idx = blockIdx.x * 256 + threadIdx.x;
    if (idx >= 3 * EDIM * DLLM) return;
    int w = idx / (EDIM * DLLM), rem = idx % (EDIM * DLLM);
    int n = rem / DLLM, k = rem % DLLM;
    const float* W = (w == 0) ? Wq : (w == 1) ? Wk : Wv;
    g_wf[idx] = __float2half_rn(W[k * EDIM + n]);
}

// ----------------------------------------------------------------------------
// Kernel 1: projection fp16 single-pass; reads fp32 X directly (reg-prefetched
// LDG -> convert -> STS); one weight per CTA; B double-buffered cp.async.
// ----------------------------------------------------------------------------
#define PA0 0              /* 128 x 144 = 18432 (fp16 A tile) */
#define PA1 18432
#define PB0 36864          /* 64 x 144 = 9216 */
#define PB1 46080
#define PR_SMEM 55296

__global__ __launch_bounds__(256, 2)
void proj_kernel(const float* __restrict__ X,
                 const float* __restrict__ bq, const float* __restrict__ bk,
                 const float* __restrict__ bv)
{
    extern __shared__ char smem[];
    const uint32_t sb = smem_u32(smem);
    const int tid = threadIdx.x, wid = tid >> 5, lane = tid & 31;
    const int g = lane >> 2, tig = lane & 3;
    const int s = blockIdx.y;
    const int w = blockIdx.x % 3;                  // siblings share X via L2
    const int row0 = (blockIdx.x / 3) * 128;
    const float* Xs = X + (size_t)s * LSEQ * DLLM + (size_t)row0 * DLLM;

    float acc[8][4];
    #pragma unroll
    for (int j = 0; j < 8; ++j)
        #pragma unroll
        for (int q = 0; q < 4; ++q) acc[j][q] = 0.f;

    // register prefetch of X chunk 0 (8 float4/thread covers 128r x 64k)
    float4 xr[8];
    #pragma unroll
    for (int t = 0; t < 8; ++t) {
        int f = tid + t * 256;
        int rr = f >> 4, c4 = (f & 15) * 4;
        xr[t] = *reinterpret_cast<const float4*>(&Xs[(size_t)rr * DLLM + c4]);
    }
    // B chunk 0
    #pragma unroll
    for (int t = 0; t < 2; ++t) {
        int f = tid + t * 256;
        int n = f >> 3, k8 = (f & 7) * 8;
        CP_ASYNC(sb + PB0 + n * 144 + k8 * 2,
                 g_wf + (size_t)w * EDIM * DLLM + (size_t)n * DLLM + k8);
    }
    CP_COMMIT();

    for (int chunk = 0; chunk < 12; ++chunk) {
        const int cur = chunk & 1;
        const uint32_t ab = sb + (cur ? PA1 : PA0);
        const uint32_t bb = sb + (cur ? PB1 : PB0);

        // convert prefetched fp32 -> fp16 A tile
        #pragma unroll
        for (int t = 0; t < 8; ++t) {
            int f = tid + t * 256;
            int rr = f >> 4, c4 = (f & 15) * 4;
            uint2 p;
            p.x = pack_h2(xr[t].x, xr[t].y);
            p.y = pack_h2(xr[t].z, xr[t].w);
            *reinterpret_cast<uint2*>(smem + (cur ? PA1 : PA0) + rr * 144 + c4 * 2) = p;
        }
        if (chunk < 11) {
            const int k0n = (chunk + 1) * 64;
            #pragma unroll
            for (int t = 0; t < 8; ++t) {
                int f = tid + t * 256;
                int rr = f >> 4, c4 = (f & 15) * 4;
                xr[t] = *reinterpret_cast<const float4*>(&Xs[(size_t)rr * DLLM + k0n + c4]);
            }
            const uint32_t bbn = sb + (cur ? PB0 : PB1);
            #pragma unroll
            for (int t = 0; t < 2; ++t) {
                int f = tid + t * 256;
                int n = f >> 3, k8 = (f & 7) * 8;
                CP_ASYNC(bbn + n * 144 + k8 * 2,
                         g_wf + (size_t)w * EDIM * DLLM + (size_t)n * DLLM + k0n + k8);
            }
            CP_COMMIT();
            CP_WAIT(1);
        } else {
            CP_WAIT(0);
        }
        __syncthreads();

        #pragma unroll
        for (int kb = 0; kb < 4; ++kb) {
            const int kby = kb * 32;
            uint32_t aF[4];
            ldsm4(aF, ldsm_addr(ab, wid * 16, kby, 144, lane));
            #pragma unroll
            for (int ntp = 0; ntp < 4; ++ntp) {
                uint32_t bF[4];
                ldsm4(bF, ldsm_addr(bb, ntp * 16, kby, 144, lane));
                mma_f16(acc[2*ntp],   aF, bF[0], bF[2]);
                mma_f16(acc[2*ntp+1], aF, bF[1], bF[3]);
            }
        }
        __syncthreads();
    }

    // epilogue (validated mapping): rows r0,r1; cols 2*tig+8j
    const int r0 = row0 + wid * 16 + g, r1 = r0 + 8;
    const float* bias = (w == 0) ? bq : (w == 1) ? bk : bv;
    const float mscale = (w == 0) ? QLOG2SCALE : 1.f;
    #pragma unroll
    for (int j = 0; j < 8; ++j) {
        int c = tig * 2 + 8 * j;
        float b0 = bias[c], b1 = bias[c + 1];
        float v00 = acc[j][0] + b0, v01 = acc[j][1] + b1;
        float v10 = acc[j][2] + b0, v11 = acc[j][3] + b1;
        if (w < 2) {
            __half* dst = (w ? g_kf : g_qf) + (size_t)s * LSEQ * EDIM;
            *reinterpret_cast<uint32_t*>(dst + (size_t)r0 * EDIM + c) =
                pack_h2(v00 * mscale, v01 * mscale);
            *reinterpret_cast<uint32_t*>(dst + (size_t)r1 * EDIM + c) =
                pack_h2(v10 * mscale, v11 * mscale);
        } else {
            float vals[4] = {v00, v01, v10, v11};
            #pragma unroll
            for (int q = 0; q < 4; ++q) {
                int e = c + (q & 1);
                int key = (q < 2) ? r0 : r1;
                g_vt[((size_t)s * EDIM + e) * LSEQ + key] = __float2half_rn(vals[q]);
            }
        }
    }
}

// ----------------------------------------------------------------------------
// Kernel 2: flash attention, full fp16, exp2-domain softmax.
// ----------------------------------------------------------------------------
#define AT_QF   0          /* 128 x 144 = 18432 */
#define AT_K0   18432
#define AT_K1   27648
#define AT_V0   36864
#define AT_V1   46080
#define AT_RED  55296
#define AT_RED2 56320
#define AT_SMEM 57344

__device__ __forceinline__ void attn_prefetch(uint32_t sb, int buf, int s, int kt,
                                              int tid) {
    const uint32_t kb = sb + (buf ? AT_K1 : AT_K0);
    const uint32_t vb = sb + (buf ? AT_V1 : AT_V0);
    #pragma unroll
    for (int t = 0; t < 2; ++t) {
        int f = tid + t * 256;
        int rr = f >> 3, c8 = (f & 7) * 8;
        const __half* src = g_kf
            + (size_t)s * LSEQ * EDIM + (size_t)(kt * 64 + rr) * EDIM + c8;
        CP_ASYNC(kb + rr * 144 + c8 * 2, src);
    }
    #pragma unroll
    for (int t = 0; t < 2; ++t) {
        int f = tid + t * 256;
        int e = f >> 3, k8 = (f & 7) * 8;
        const __half* src = g_vt
            + ((size_t)s * EDIM + e) * LSEQ + kt * 64 + k8;
        CP_ASYNC(vb + e * 144 + k8 * 2, src);
    }
    CP_COMMIT();
}

__global__ __launch_bounds__(256, 2)
void attn_kernel()
{
    extern __shared__ char smem[];
    const uint32_t sb = smem_u32(smem);
    const int tid = threadIdx.x, wid = tid >> 5, lane = tid & 31;
    const int g = lane >> 2, tig = lane & 3;
    const int s = blockIdx.y, row0 = blockIdx.x * 128;

    attn_prefetch(sb, 0, s, 0, tid);

    const __half* Qf = g_qf + (size_t)s * LSEQ * EDIM + (size_t)row0 * EDIM;
    #pragma unroll
    for (int t = 0; t < 4; ++t) {
        int f = tid + t * 256;
        int rr = f >> 3, c8 = (f & 7) * 8;
        *reinterpret_cast<uint4*>(smem + AT_QF + rr * 144 + c8 * 2) =
            *reinterpret_cast<const uint4*>(Qf + (size_t)rr * EDIM + c8);
    }

    float O[8][4];
    #pragma unroll
    for (int j = 0; j < 8; ++j)
        #pragma unroll
        for (int q = 0; q < 4; ++q) O[j][q] = 0.f;
    float m0 = -1e30f, m1 = -1e30f, l0 = 0.f, l1 = 0.f;

    for (int kt = 0; kt < LSEQ / 64; ++kt) {
        const int cur = kt & 1;
        if (kt < LSEQ / 64 - 1) {
            attn_prefetch(sb, 1 - cur, s, kt + 1, tid);
            CP_WAIT(1);
        } else {
            CP_WAIT(0);
        }
        __syncthreads();

        const uint32_t kf = sb + (cur ? AT_K1 : AT_K0);
        const uint32_t vf = sb + (cur ? AT_V1 : AT_V0);

        // ---- S(16x64) = Q K^T (log2-domain scores) ----
        float S[8][4];
        #pragma unroll
        for (int nt = 0; nt < 8; ++nt)
            #pragma unroll
            for (int q = 0; q < 4; ++q) S[nt][q] = 0.f;

        #pragma unroll
        for (int kb = 0; kb < 4; ++kb) {
            const int kby = kb * 32;
            uint32_t aF[4];
            ldsm4(aF, ldsm_addr(sb + AT_QF, wid * 16, kby, 144, lane));
            #pragma unroll
            for (int ntp = 0; ntp < 4; ++ntp) {
                uint32_t bF[4];
                ldsm4(bF, ldsm_addr(kf, ntp * 16, kby, 144, lane));
                mma_f16(S[2*ntp],   aF, bF[0], bF[2]);
                mma_f16(S[2*ntp+1], aF, bF[1], bF[3]);
            }
        }

        // ---- online softmax (base-2) ----
        float mx0 = -1e30f, mx1 = -1e30f;
        #pragma unroll
        for (int nt = 0; nt < 8; ++nt) {
            mx0 = fmaxf(mx0, fmaxf(S[nt][0], S[nt][1]));
            mx1 = fmaxf(mx1, fmaxf(S[nt][2], S[nt][3]));
        }
        mx0 = fmaxf(mx0, __shfl_xor_sync(0xffffffffu, mx0, 1));
        mx0 = fmaxf(mx0, __shfl_xor_sync(0xffffffffu, mx0, 2));
        mx1 = fmaxf(mx1, __shfl_xor_sync(0xffffffffu, mx1, 1));
        mx1 = fmaxf(mx1, __shfl_xor_sync(0xffffffffu, mx1, 2));
        float mn0 = fmaxf(m0, mx0), mn1 = fmaxf(m1, mx1);
        float a0 = exp2f(m0 - mn0), a1 = exp2f(m1 - mn1);
        m0 = mn0; m1 = mn1;
        float s0 = 0.f, s1 = 0.f;
        #pragma unroll
        for (int nt = 0; nt < 8; ++nt) {
            S[nt][0] = exp2f(S[nt][0] - mn0);
            S[nt][1] = exp2f(S[nt][1] - mn0);
            S[nt][2] = exp2f(S[nt][2] - mn1);
            S[nt][3] = exp2f(S[nt][3] - mn1);
            s0 += S[nt][0] + S[nt][1];
            s1 += S[nt][2] + S[nt][3];
        }
        s0 += __shfl_xor_sync(0xffffffffu, s0, 1);
        s0 += __shfl_xor_sync(0xffffffffu, s0, 2);
        s1 += __shfl_xor_sync(0xffffffffu, s1, 1);
        s1 += __shfl_xor_sync(0xffffffffu, s1, 2);
        l0 = l0 * a0 + s0;
        l1 = l1 * a1 + s1;

        // rescale O
        #pragma unroll
        for (int j = 0; j < 8; ++j) {
            O[j][0] *= a0; O[j][1] *= a0;
            O[j][2] *= a1; O[j][3] *= a1;
        }

        // ---- register P pack (fp16) + PV ----
        #pragma unroll
        for (int kb = 0; kb < 4; ++kb) {
            uint32_t pf[4];
            pf[0] = pack_h2(S[2*kb][0],   S[2*kb][1]);
            pf[1] = pack_h2(S[2*kb][2],   S[2*kb][3]);
            pf[2] = pack_h2(S[2*kb+1][0], S[2*kb+1][1]);
            pf[3] = pack_h2(S[2*kb+1][2], S[2*kb+1][3]);
            const int kby = kb * 32;
            #pragma unroll
            for (int ntp = 0; ntp < 4; ++ntp) {
                uint32_t vF[4];
                ldsm4(vF, ldsm_addr(vf, ntp * 16, kby, 144, lane));
                mma_f16(O[2*ntp],   pf, vF[0], vF[2]);
                mma_f16(O[2*ntp+1], pf, vF[1], vF[3]);
            }
        }
        __syncthreads();
    }

    // ---- finalize ----
    const float inv0 = 1.f / l0, inv1 = 1.f / l1;
    const int r0 = row0 + wid * 16 + g, r1 = r0 + 8;
    float* Og = g_o + (size_t)s * LSEQ * EDIM;
    float lsum = 0.f, lsq = 0.f;
    #pragma unroll
    for (int j = 0; j < 8; ++j) {
        int c = tig * 2 + 8 * j;
        float o00 = O[j][0] * inv0, o01 = O[j][1] * inv0;
        float o10 = O[j][2] * inv1, o11 = O[j][3] * inv1;
        *reinterpret_cast<float2*>(Og + (size_t)r0 * EDIM + c) = make_float2(o00, o01);
        *reinterpret_cast<float2*>(Og + (size_t)r1 * EDIM + c) = make_float2(o10, o11);
        lsum += o00 + o01 + o10 + o11;
        lsq  += o00*o00 + o01*o01 + o10*o10 + o11*o11;
    }

    float* red  = reinterpret_cast<float*>(smem + AT_RED);
    float* red2 = reinterpret_cast<float*>(smem + AT_RED2);
    __syncthreads();
    red[tid] = lsum; red2[tid] = lsq;
    __syncthreads();
    #pragma unroll
    for (int st = 128; st; st >>= 1) {
        if (tid < st) { red[tid] += red[tid + st]; red2[tid] += red2[tid + st]; }
        __syncthreads();
    }
    if (tid == 0) g_part[s * NQT + blockIdx.x] = make_float2(red[0], red2[0]);
}

// ---------------- kernels 3/4 ----------------
__global__ void stats_kernel()
{
    const int s = blockIdx.x, t = threadIdx.x;
    float sum = 0.f, sq = 0.f;
    if (t < NQT) { float2 p = g_part[s * NQT + t]; sum = p.x; sq = p.y; }
    #pragma unroll
    for (int off = 16; off; off >>= 1) {
        sum += __shfl_xor_sync(0xffffffffu, sum, off);
        sq  += __shfl_xor_sync(0xffffffffu, sq,  off);
    }
    if (t == 0) {
        const float n = (float)(LSEQ * EDIM);
        float mu = sum / n;
        float var = sq / n - mu * mu;
        g_stats[s] = make_float2(mu, rsqrtf(var + EPS));
    }
}

__global__ void norm_kernel(float* __restrict__ out)
{
    int base = (blockIdx.x * 256 + threadIdx.x) * 4;
    int s = base / (LSEQ * EDIM);
    float2 st = g_stats[s];
    const float4 o = *reinterpret_cast<const float4*>(&g_o[base]);
    float4 rr;
    rr.x = (o.x - st.x) * st.y; rr.y = (o.y - st.x) * st.y;
    rr.z = (o.z - st.x) * st.y; rr.w = (o.w - st.x) * st.y;
    *reinterpret_cast<float4*>(&out[base]) = rr;
}

// ---------------- host ----------------
extern "C" void kernel_launch(void* const* d_in, const int* in_sizes, int n_in,
                              void* d_out, int out_size)
{
    const float* info = (const float*)d_in[0];
    const float* Wq = (const float*)d_in[1];
    const float* bq = (const float*)d_in[2];
    const float* Wk = (const float*)d_in[3];
    const float* bk = (const float*)d_in[4];
    const float* Wv = (const float*)d_in[5];
    const float* bv = (const float*)d_in[6];
    float* out = (float*)d_out;

    cudaFuncSetAttribute(proj_kernel, cudaFuncAttributeMaxDynamicSharedMemorySize, PR_SMEM);
    cudaFuncSetAttribute(attn_kernel, cudaFuncAttributeMaxDynamicSharedMemorySize, AT_SMEM);

    wsplit_kernel<<<(3 * EDIM * DLLM + 255) / 256, 256>>>(Wq, Wk, Wv);
    proj_kernel<<<dim3(3 * (LSEQ / 128), NSLICE), 256, PR_SMEM>>>(info, bq, bk, bv);
    attn_kernel<<<dim3(NQT, NSLICE), 256, AT_SMEM>>>();
    stats_kernel<<<NSLICE, 32>>>();
    norm_kernel<<<NSLICE * LSEQ * EDIM / 1024, 256>>>(out);
}

// round 15
// speedup vs baseline: 2.2724x; 1.0149x over previous
#include <cuda_runtime.h>
#include <cuda_fp16.h>
#include <math.h>
#include <stdint.h>

#define NSLICE 16
#define LSEQ   2048
#define DLLM   768
#define EDIM   64
#define EPS    1e-5f
#define NQT    16
#define QLOG2SCALE (0.125f * 1.4426950408889634f)

// ---------------- device scratch ----------------
__device__ float g_o[NSLICE*LSEQ*EDIM];
__device__ __half g_qf[NSLICE*LSEQ*EDIM];    // q*0.125*log2e fp16
__device__ __half g_kf[NSLICE*LSEQ*EDIM];    // k fp16
__device__ __half g_vt[NSLICE*EDIM*LSEQ];    // V^T [s][e][key] fp16
__device__ __half g_wf[3*EDIM*DLLM];         // W^T [w][n][k] fp16
__device__ float2 g_part[NSLICE*NQT];

// ---------------- helpers (validated) ----------------
__device__ __forceinline__ uint32_t smem_u32(const void* p) {
    uint32_t a;
    asm("{ .reg .u64 t; cvta.to.shared.u64 t, %1; cvt.u32.u64 %0, t; }" : "=r"(a) : "l"(p));
    return a;
}
__device__ __forceinline__ void ldsm4(uint32_t* r, uint32_t addr) {
    asm volatile("ldmatrix.sync.aligned.m8n8.x4.shared.b16 {%0,%1,%2,%3}, [%4];"
                 : "=r"(r[0]), "=r"(r[1]), "=r"(r[2]), "=r"(r[3]) : "r"(addr) : "memory");
}
__device__ __forceinline__ uint32_t ldsm_addr(uint32_t base, int row0, int kbyte,
                                              int pitch, int lane) {
    return base + (row0 + (lane & 15)) * pitch + kbyte + (lane >> 4) * 16;
}
__device__ __forceinline__ void mma_f16(float* d, const uint32_t* a,
                                        uint32_t b0, uint32_t b1) {
    asm volatile("mma.sync.aligned.m16n8k16.row.col.f32.f16.f16.f32 "
        "{%0,%1,%2,%3}, {%4,%5,%6,%7}, {%8,%9}, {%0,%1,%2,%3};"
        : "+f"(d[0]), "+f"(d[1]), "+f"(d[2]), "+f"(d[3])
        : "r"(a[0]), "r"(a[1]), "r"(a[2]), "r"(a[3]), "r"(b0), "r"(b1));
}
__device__ __forceinline__ uint32_t pack_h2(float x0, float x1) {
    __half2 h = __floats2half2_rn(x0, x1);
    return *reinterpret_cast<uint32_t*>(&h);
}
__device__ __forceinline__ uint32_t pack_exp2(float x0, float x1) {
    __half2 h = h2exp2(__floats2half2_rn(x0, x1));
    return *reinterpret_cast<uint32_t*>(&h);
}
#define CP_ASYNC(dst, src) \
    asm volatile("cp.async.cg.shared.global [%0], [%1], 16;" :: "r"(dst), "l"(src) : "memory")
#define CP_COMMIT() asm volatile("cp.async.commit_group;" ::: "memory")
#define CP_WAIT(n)  asm volatile("cp.async.wait_group %0;" :: "n"(n) : "memory")

// ---------------- kernel 0: W^T fp16 ----------------
__global__ void wsplit_kernel(const float* __restrict__ Wq,
                              const float* __restrict__ Wk,
                              const float* __restrict__ Wv) {
    int idx = blockIdx.x * 256 + threadIdx.x;
    if (idx >= 3 * EDIM * DLLM) return;
    int w = idx / (EDIM * DLLM), rem = idx % (EDIM * DLLM);
    int n = rem / DLLM, k = rem % DLLM;
    const float* W = (w == 0) ? Wq : (w == 1) ? Wk : Wv;
    g_wf[idx] = __float2half_rn(W[k * EDIM + n]);
}

// ----------------------------------------------------------------------------
// Kernel 1: projection (unchanged from validated round 14)
// ----------------------------------------------------------------------------
#define PA0 0
#define PA1 18432
#define PB0 36864
#define PB1 46080
#define PR_SMEM 55296

__global__ __launch_bounds__(256, 2)
void proj_kernel(const float* __restrict__ X,
                 const float* __restrict__ bq, const float* __restrict__ bk,
                 const float* __restrict__ bv)
{
    extern __shared__ char smem[];
    const uint32_t sb = smem_u32(smem);
    const int tid = threadIdx.x, wid = tid >> 5, lane = tid & 31;
    const int g = lane >> 2, tig = lane & 3;
    const int s = blockIdx.y;
    const int w = blockIdx.x % 3;
    const int row0 = (blockIdx.x / 3) * 128;
    const float* Xs = X + (size_t)s * LSEQ * DLLM + (size_t)row0 * DLLM;

    float acc[8][4];
    #pragma unroll
    for (int j = 0; j < 8; ++j)
        #pragma unroll
        for (int q = 0; q < 4; ++q) acc[j][q] = 0.f;

    float4 xr[8];
    #pragma unroll
    for (int t = 0; t < 8; ++t) {
        int f = tid + t * 256;
        int rr = f >> 4, c4 = (f & 15) * 4;
        xr[t] = *reinterpret_cast<const float4*>(&Xs[(size_t)rr * DLLM + c4]);
    }
    #pragma unroll
    for (int t = 0; t < 2; ++t) {
        int f = tid + t * 256;
        int n = f >> 3, k8 = (f & 7) * 8;
        CP_ASYNC(sb + PB0 + n * 144 + k8 * 2,
                 g_wf + (size_t)w * EDIM * DLLM + (size_t)n * DLLM + k8);
    }
    CP_COMMIT();

    for (int chunk = 0; chunk < 12; ++chunk) {
        const int cur = chunk & 1;
        const uint32_t ab = sb + (cur ? PA1 : PA0);
        const uint32_t bb = sb + (cur ? PB1 : PB0);

        #pragma unroll
        for (int t = 0; t < 8; ++t) {
            int f = tid + t * 256;
            int rr = f >> 4, c4 = (f & 15) * 4;
            uint2 p;
            p.x = pack_h2(xr[t].x, xr[t].y);
            p.y = pack_h2(xr[t].z, xr[t].w);
            *reinterpret_cast<uint2*>(smem + (cur ? PA1 : PA0) + rr * 144 + c4 * 2) = p;
        }
        if (chunk < 11) {
            const int k0n = (chunk + 1) * 64;
            #pragma unroll
            for (int t = 0; t < 8; ++t) {
                int f = tid + t * 256;
                int rr = f >> 4, c4 = (f & 15) * 4;
                xr[t] = *reinterpret_cast<const float4*>(&Xs[(size_t)rr * DLLM + k0n + c4]);
            }
            const uint32_t bbn = sb + (cur ? PB0 : PB1);
            #pragma unroll
            for (int t = 0; t < 2; ++t) {
                int f = tid + t * 256;
                int n = f >> 3, k8 = (f & 7) * 8;
                CP_ASYNC(bbn + n * 144 + k8 * 2,
                         g_wf + (size_t)w * EDIM * DLLM + (size_t)n * DLLM + k0n + k8);
            }
            CP_COMMIT();
            CP_WAIT(1);
        } else {
            CP_WAIT(0);
        }
        __syncthreads();

        #pragma unroll
        for (int kb = 0; kb < 4; ++kb) {
            const int kby = kb * 32;
            uint32_t aF[4];
            ldsm4(aF, ldsm_addr(ab, wid * 16, kby, 144, lane));
            #pragma unroll
            for (int ntp = 0; ntp < 4; ++ntp) {
                uint32_t bF[4];
                ldsm4(bF, ldsm_addr(bb, ntp * 16, kby, 144, lane));
                mma_f16(acc[2*ntp],   aF, bF[0], bF[2]);
                mma_f16(acc[2*ntp+1], aF, bF[1], bF[3]);
            }
        }
        __syncthreads();
    }

    const int r0 = row0 + wid * 16 + g, r1 = r0 + 8;
    const float* bias = (w == 0) ? bq : (w == 1) ? bk : bv;
    const float mscale = (w == 0) ? QLOG2SCALE : 1.f;
    #pragma unroll
    for (int j = 0; j < 8; ++j) {
        int c = tig * 2 + 8 * j;
        float b0 = bias[c], b1 = bias[c + 1];
        float v00 = acc[j][0] + b0, v01 = acc[j][1] + b1;
        float v10 = acc[j][2] + b0, v11 = acc[j][3] + b1;
        if (w < 2) {
            __half* dst = (w ? g_kf : g_qf) + (size_t)s * LSEQ * EDIM;
            *reinterpret_cast<uint32_t*>(dst + (size_t)r0 * EDIM + c) =
                pack_h2(v00 * mscale, v01 * mscale);
            *reinterpret_cast<uint32_t*>(dst + (size_t)r1 * EDIM + c) =
                pack_h2(v10 * mscale, v11 * mscale);
        } else {
            float vals[4] = {v00, v01, v10, v11};
            #pragma unroll
            for (int q = 0; q < 4; ++q) {
                int e = c + (q & 1);
                int key = (q < 2) ? r0 : r1;
                g_vt[((size_t)s * EDIM + e) * LSEQ + key] = __float2half_rn(vals[q]);
            }
        }
    }
}

// ----------------------------------------------------------------------------
// Kernel 2: flash attention; h2exp2 softmax; l via ones-column MMA.
// V smem tile = 80 rows x 144 (rows 64-79: row 64 = 1.0, rest 0).
// ----------------------------------------------------------------------------
#define AT_QF   0          /* 128 x 144 = 18432 */
#define AT_K0   18432      /* 64 x 144 = 9216 */
#define AT_K1   27648
#define AT_V0   36864      /* 80 x 144 = 11520 */
#define AT_V1   48384
#define AT_RED  59904
#define AT_RED2 60928
#define AT_SMEM 61952

__device__ __forceinline__ void attn_prefetch(uint32_t sb, int buf, int s, int kt,
                                              int tid) {
    const uint32_t kb = sb + (buf ? AT_K1 : AT_K0);
    const uint32_t vb = sb + (buf ? AT_V1 : AT_V0);
    #pragma unroll
    for (int t = 0; t < 2; ++t) {
        int f = tid + t * 256;
        int rr = f >> 3, c8 = (f & 7) * 8;
        const __half* src = g_kf
            + (size_t)s * LSEQ * EDIM + (size_t)(kt * 64 + rr) * EDIM + c8;
        CP_ASYNC(kb + rr * 144 + c8 * 2, src);
    }
    #pragma unroll
    for (int t = 0; t < 2; ++t) {
        int f = tid + t * 256;
        int e = f >> 3, k8 = (f & 7) * 8;
        const __half* src = g_vt
            + ((size_t)s * EDIM + e) * LSEQ + kt * 64 + k8;
        CP_ASYNC(vb + e * 144 + k8 * 2, src);
    }
    CP_COMMIT();
}

__global__ __launch_bounds__(256, 2)
void attn_kernel()
{
    extern __shared__ char smem[];
    const uint32_t sb = smem_u32(smem);
    const int tid = threadIdx.x, wid = tid >> 5, lane = tid & 31;
    const int g = lane >> 2, tig = lane & 3;
    const int s = blockIdx.y, row0 = blockIdx.x * 128;

    attn_prefetch(sb, 0, s, 0, tid);

    // init ones/zero rows (64-79) of BOTH V buffers: 16 rows x 36 uint32 x 2
    for (int i = tid; i < 16 * 36 * 2; i += 256) {
        int buf = i >= 16 * 36;
        int ii = i & (16 * 36 - 1);
        int rr = 64 + ii / 36, c4 = (ii % 36) * 4;   // byte col = c4
        uint32_t val = (rr == 64) ? 0x3C003C00u : 0u;  // half2(1,1) or 0
        *reinterpret_cast<uint32_t*>(smem + (buf ? AT_V1 : AT_V0) + rr * 144 + c4) = val;
    }

    const __half* Qf = g_qf + (size_t)s * LSEQ * EDIM + (size_t)row0 * EDIM;
    #pragma unroll
    for (int t = 0; t < 4; ++t) {
        int f = tid + t * 256;
        int rr = f >> 3, c8 = (f & 7) * 8;
        *reinterpret_cast<uint4*>(smem + AT_QF + rr * 144 + c8 * 2) =
            *reinterpret_cast<const uint4*>(Qf + (size_t)rr * EDIM + c8);
    }

    float O[8][4], O5[4];
    #pragma unroll
    for (int j = 0; j < 8; ++j)
        #pragma unroll
        for (int q = 0; q < 4; ++q) O[j][q] = 0.f;
    #pragma unroll
    for (int q = 0; q < 4; ++q) O5[q] = 0.f;
    float m0 = -1e30f, m1 = -1e30f;

    for (int kt = 0; kt < LSEQ / 64; ++kt) {
        const int cur = kt & 1;
        if (kt < LSEQ / 64 - 1) {
            attn_prefetch(sb, 1 - cur, s, kt + 1, tid);
            CP_WAIT(1);
        } else {
            CP_WAIT(0);
        }
        __syncthreads();

        const uint32_t kf = sb + (cur ? AT_K1 : AT_K0);
        const uint32_t vf = sb + (cur ? AT_V1 : AT_V0);

        // ---- S(16x64) = Q K^T (log2-domain) ----
        float S[8][4];
        #pragma unroll
        for (int nt = 0; nt < 8; ++nt)
            #pragma unroll
            for (int q = 0; q < 4; ++q) S[nt][q] = 0.f;

        #pragma unroll
        for (int kb = 0; kb < 4; ++kb) {
            const int kby = kb * 32;
            uint32_t aF[4];
            ldsm4(aF, ldsm_addr(sb + AT_QF, wid * 16, kby, 144, lane));
            #pragma unroll
            for (int ntp = 0; ntp < 4; ++ntp) {
                uint32_t bF[4];
                ldsm4(bF, ldsm_addr(kf, ntp * 16, kby, 144, lane));
                mma_f16(S[2*ntp],   aF, bF[0], bF[2]);
                mma_f16(S[2*ntp+1], aF, bF[1], bF[3]);
            }
        }

        // ---- online max (base-2) ----
        float mx0 = -1e30f, mx1 = -1e30f;
        #pragma unroll
        for (int nt = 0; nt < 8; ++nt) {
            mx0 = fmaxf(mx0, fmaxf(S[nt][0], S[nt][1]));
            mx1 = fmaxf(mx1, fmaxf(S[nt][2], S[nt][3]));
        }
        mx0 = fmaxf(mx0, __shfl_xor_sync(0xffffffffu, mx0, 1));
        mx0 = fmaxf(mx0, __shfl_xor_sync(0xffffffffu, mx0, 2));
        mx1 = fmaxf(mx1, __shfl_xor_sync(0xffffffffu, mx1, 1));
        mx1 = fmaxf(mx1, __shfl_xor_sync(0xffffffffu, mx1, 2));
        float mn0 = fmaxf(m0, mx0), mn1 = fmaxf(m1, mx1);
        float a0 = exp2f(m0 - mn0), a1 = exp2f(m1 - mn1);
        m0 = mn0; m1 = mn1;

        // rescale O (+ ones column)
        #pragma unroll
        for (int j = 0; j < 8; ++j) {
            O[j][0] *= a0; O[j][1] *= a0;
            O[j][2] *= a1; O[j][3] *= a1;
        }
        O5[0] *= a0; O5[1] *= a0; O5[2] *= a1; O5[3] *= a1;

        // ---- P = exp2(S - m) via h2exp2, PV + ones-column ----
        #pragma unroll
        for (int kb = 0; kb < 4; ++kb) {
            uint32_t pf[4];
            pf[0] = pack_exp2(S[2*kb][0] - mn0,   S[2*kb][1] - mn0);
            pf[1] = pack_exp2(S[2*kb][2] - mn1,   S[2*kb][3] - mn1);
            pf[2] = pack_exp2(S[2*kb+1][0] - mn0, S[2*kb+1][1] - mn0);
            pf[3] = pack_exp2(S[2*kb+1][2] - mn1, S[2*kb+1][3] - mn1);
            const int kby = kb * 32;
            #pragma unroll
            for (int ntp = 0; ntp < 4; ++ntp) {
                uint32_t vF[4];
                ldsm4(vF, ldsm_addr(vf, ntp * 16, kby, 144, lane));
                mma_f16(O[2*ntp],   pf, vF[0], vF[2]);
                mma_f16(O[2*ntp+1], pf, vF[1], vF[3]);
            }
            uint32_t vE[4];
            ldsm4(vE, ldsm_addr(vf, 64, kby, 144, lane));
            mma_f16(O5, pf, vE[0], vE[2]);
        }
        __syncthreads();
    }

    // ---- finalize: l from ones column (col 0 -> tig==0 lanes) ----
    float l0 = __shfl_sync(0xffffffffu, O5[0], lane & ~3);
    float l1 = __shfl_sync(0xffffffffu, O5[2], lane & ~3);
    const float inv0 = 1.f / l0, inv1 = 1.f / l1;
    const int r0 = row0 + wid * 16 + g, r1 = r0 + 8;
    float* Og = g_o + (size_t)s * LSEQ * EDIM;
    float lsum = 0.f, lsq = 0.f;
    #pragma unroll
    for (int j = 0; j < 8; ++j) {
        int c = tig * 2 + 8 * j;
        float o00 = O[j][0] * inv0, o01 = O[j][1] * inv0;
        float o10 = O[j][2] * inv1, o11 = O[j][3] * inv1;
        *reinterpret_cast<float2*>(Og + (size_t)r0 * EDIM + c) = make_float2(o00, o01);
        *reinterpret_cast<float2*>(Og + (size_t)r1 * EDIM + c) = make_float2(o10, o11);
        lsum += o00 + o01 + o10 + o11;
        lsq  += o00*o00 + o01*o01 + o10*o10 + o11*o11;
    }

    float* red  = reinterpret_cast<float*>(smem + AT_RED);
    float* red2 = reinterpret_cast<float*>(smem + AT_RED2);
    __syncthreads();
    red[tid] = lsum; red2[tid] = lsq;
    __syncthreads();
    #pragma unroll
    for (int st = 128; st; st >>= 1) {
        if (tid < st) { red[tid] += red[tid + st]; red2[tid] += red2[tid + st]; }
        __syncthreads();
    }
    if (tid == 0) g_part[s * NQT + blockIdx.x] = make_float2(red[0], red2[0]);
}

// ---------------- kernel 3: fused stats + normalize ----------------
__global__ void norm_kernel(float* __restrict__ out)
{
    __shared__ float2 st_sh;
    const int blk = blockIdx.x;
    const int s = blk >> 7;                     // 128 blocks per slice
    if (threadIdx.x < 32) {
        float sum = 0.f, sq = 0.f;
        if (threadIdx.x < NQT) {
            float2 p = g_part[s * NQT + threadIdx.x];
            sum = p.x; sq = p.y;
        }
        #pragma unroll
        for (int off = 16; off; off >>= 1) {
            sum += __shfl_xor_sync(0xffffffffu, sum, off);
            sq  += __shfl_xor_sync(0xffffffffu, sq,  off);
        }
        if (threadIdx.x == 0) {
            const float n = (float)(LSEQ * EDIM);
            float mu = sum / n;
            float var = sq / n - mu * mu;
            st_sh = make_float2(mu, rsqrtf(var + EPS));
        }
    }
    __syncthreads();
    float2 st = st_sh;
    int base = (blk * 256 + threadIdx.x) * 4;
    const float4 o = *reinterpret_cast<const float4*>(&g_o[base]);
    float4 rr;
    rr.x = (o.x - st.x) * st.y; rr.y = (o.y - st.x) * st.y;
    rr.z = (o.z - st.x) * st.y; rr.w = (o.w - st.x) * st.y;
    *reinterpret_cast<float4*>(&out[base]) = rr;
}

// ---------------- host ----------------
extern "C" void kernel_launch(void* const* d_in, const int* in_sizes, int n_in,
                              void* d_out, int out_size)
{
    const float* info = (const float*)d_in[0];
    const float* Wq = (const float*)d_in[1];
    const float* bq = (const float*)d_in[2];
    const float* Wk = (const float*)d_in[3];
    const float* bk = (const float*)d_in[4];
    const float* Wv = (const float*)d_in[5];
    const float* bv = (const float*)d_in[6];
    float* out = (float*)d_out;

    cudaFuncSetAttribute(proj_kernel, cudaFuncAttributeMaxDynamicSharedMemorySize, PR_SMEM);
    cudaFuncSetAttribute(attn_kernel, cudaFuncAttributeMaxDynamicSharedMemorySize, AT_SMEM);

    wsplit_kernel<<<(3 * EDIM * DLLM + 255) / 256, 256>>>(Wq, Wk, Wv);
    proj_kernel<<<dim3(3 * (LSEQ / 128), NSLICE), 256, PR_SMEM>>>(info, bq, bk, bv);
    attn_kernel<<<dim3(NQT, NSLICE), 256, AT_SMEM>>>();
    norm_kernel<<<NSLICE * LSEQ * EDIM / 1024, 256>>>(out);
}